// round 2
// baseline (speedup 1.0000x reference)
#include <cuda_runtime.h>
#include <cuda_bf16.h>

// Problem constants (from reference)
#define NODE_DIM   128
#define GATE_HID   64
#define OUT_DIM    128
#define NUM_GRAPHS 16384

#define CHUNK      128   // nodes per block in the fused pass
#define THREADS    256

// Scratch: per-graph sum of g*h  [B,128]  and per-graph sum of g  [B]
__device__ float g_S[NUM_GRAPHS * OUT_DIM];
__device__ float g_cnt[NUM_GRAPHS];

// ---------------------------------------------------------------------------
// batch may arrive as int32 (JAX default, x64 off) or int64. Detect by layout:
// int32 view index N-1 (N even -> odd index) is the HIGH word of an int64
// element (== 0 since ids are small non-negative), but the last real value
// (~16383) under int32 layout.
// ---------------------------------------------------------------------------
__device__ __forceinline__ int batch_at(const void* p, int i, bool is64) {
    if (is64) return (int)(((const long long*)p)[i]);
    return ((const int*)p)[i];
}

// ---------------------------------------------------------------------------
__global__ void zero_kernel() {
    int idx = blockIdx.x * blockDim.x + threadIdx.x;
    if (idx < NUM_GRAPHS * OUT_DIM) g_S[idx] = 0.0f;
    if (idx < NUM_GRAPHS)           g_cnt[idx] = 0.0f;
}

// ---------------------------------------------------------------------------
// Fused pass: per 128-node chunk
//   1) stage h tile + weights in smem
//   2) hidden = relu(h @ Wg1 + bg1); gate = sigmoid(hidden @ Wg2 + bg2)
//   3) segment-accumulate  S[b] += g*h,  cnt[b] += g   (batch is sorted)
// ---------------------------------------------------------------------------
#define H_STRIDE 129   // pad to kill bank conflicts (delta-4-node -> bank +4)

__global__ __launch_bounds__(THREADS, 2)
void fused_kernel(const float* __restrict__ h_nodes,
                  const void*  __restrict__ batch,
                  const float* __restrict__ Wg1,
                  const float* __restrict__ bg1,
                  const float* __restrict__ Wg2,
                  const float* __restrict__ bg2,
                  int N)
{
    extern __shared__ float smem[];
    float* sh_h    = smem;                    // 128*129
    float* sh_W    = sh_h + CHUNK * H_STRIDE; // 128*64
    float* sh_bg1  = sh_W + NODE_DIM * GATE_HID; // 64
    float* sh_Wg2  = sh_bg1 + GATE_HID;          // 64
    float* sh_gp   = sh_Wg2 + GATE_HID;          // 128*8
    float* sh_gate = sh_gp + CHUNK * 8;          // 128
    int*   sh_b    = (int*)(sh_gate + CHUNK);    // 128

    const int tid  = threadIdx.x;
    const int base = blockIdx.x * CHUNK;
    const int nn   = min(CHUNK, N - base);

    const bool is64 = (((const int*)batch)[N - 1] == 0);

    // stage weights
    #pragma unroll 4
    for (int i = tid; i < NODE_DIM * GATE_HID; i += THREADS) sh_W[i] = Wg1[i];
    if (tid < GATE_HID) { sh_bg1[tid] = bg1[tid]; sh_Wg2[tid] = Wg2[tid]; }

    // stage h tile (float4 coalesced), zero-fill tail nodes
    for (int i = tid; i < CHUNK * (NODE_DIM / 4); i += THREADS) {
        int n = i >> 5, q = i & 31;
        float4 v = make_float4(0.f, 0.f, 0.f, 0.f);
        if (n < nn) v = ((const float4*)h_nodes)[(size_t)(base + n) * (NODE_DIM / 4) + q];
        float* dst = sh_h + n * H_STRIDE + q * 4;
        dst[0] = v.x; dst[1] = v.y; dst[2] = v.z; dst[3] = v.w;
    }
    // stage batch ids
    if (tid < CHUNK) sh_b[tid] = (tid < nn) ? batch_at(batch, base + tid, is64) : 0;
    __syncthreads();

    // ---- gate MLP: hidden[128,64] ----
    // thread = (ng, cg): 4 nodes x 8 hidden cols
    const int ng = tid >> 3;         // 0..31
    const int cg = tid & 7;          // 0..7
    const int jb = cg * 8;
    const float* hp = sh_h + ng * 4 * H_STRIDE;

    float acc[4][8];
    #pragma unroll
    for (int i = 0; i < 4; ++i)
        #pragma unroll
        for (int j = 0; j < 8; ++j) acc[i][j] = sh_bg1[jb + j];

    #pragma unroll 4
    for (int k = 0; k < NODE_DIM; ++k) {
        float hv0 = hp[0 * H_STRIDE + k];
        float hv1 = hp[1 * H_STRIDE + k];
        float hv2 = hp[2 * H_STRIDE + k];
        float hv3 = hp[3 * H_STRIDE + k];
        const float4* wrow = (const float4*)(sh_W + k * GATE_HID + jb);
        float4 wa = wrow[0];
        float4 wb = wrow[1];
        float w[8] = {wa.x, wa.y, wa.z, wa.w, wb.x, wb.y, wb.z, wb.w};
        #pragma unroll
        for (int j = 0; j < 8; ++j) {
            acc[0][j] = fmaf(hv0, w[j], acc[0][j]);
            acc[1][j] = fmaf(hv1, w[j], acc[1][j]);
            acc[2][j] = fmaf(hv2, w[j], acc[2][j]);
            acc[3][j] = fmaf(hv3, w[j], acc[3][j]);
        }
    }

    // relu + partial dot with Wg2
    #pragma unroll
    for (int i = 0; i < 4; ++i) {
        float gp = 0.0f;
        #pragma unroll
        for (int j = 0; j < 8; ++j)
            gp = fmaf(fmaxf(acc[i][j], 0.0f), sh_Wg2[jb + j], gp);
        sh_gp[(ng * 4 + i) * 8 + cg] = gp;
    }
    __syncthreads();

    // reduce 8 partials + sigmoid
    if (tid < CHUNK) {
        float s = bg2[0];
        #pragma unroll
        for (int c = 0; c < 8; ++c) s += sh_gp[tid * 8 + c];
        sh_gate[tid] = 1.0f / (1.0f + __expf(-s));
    }
    __syncthreads();

    // ---- segment accumulate (batch sorted -> register acc, flush on change)
    {
        const int half = tid >> 7;            // 0 or 1
        const int d    = tid & 127;
        const int ns   = half * 64;
        const int ne   = min(ns + 64, nn);
        if (ns < ne) {
            int   cur  = sh_b[ns];
            float accS = 0.0f, accG = 0.0f;
            for (int n = ns; n < ne; ++n) {
                int b = sh_b[n];
                if (b != cur) {
                    atomicAdd(&g_S[(size_t)cur * OUT_DIM + d], accS);
                    if (d == 0) atomicAdd(&g_cnt[cur], accG);
                    accS = 0.0f; accG = 0.0f; cur = b;
                }
                float g = sh_gate[n];
                accS = fmaf(g, sh_h[n * H_STRIDE + d], accS);
                if (d == 0) accG += g;
            }
            atomicAdd(&g_S[(size_t)cur * OUT_DIM + d], accS);
            if (d == 0) atomicAdd(&g_cnt[cur], accG);
        }
    }
}

// ---------------------------------------------------------------------------
// Final: out[b] = S[b] @ W_p + cnt[b] * b_p     [16384,128] @ [128,128]
// 256 blocks x 64 graphs; W_p staged in smem once per block.
// ---------------------------------------------------------------------------
#define FIN_GRAPHS 64

__global__ __launch_bounds__(THREADS, 1)
void final_kernel(const float* __restrict__ Wp,
                  const float* __restrict__ bp,
                  float* __restrict__ out)
{
    extern __shared__ float sWp[];   // 128*128 = 64KB
    const int tid = threadIdx.x;
    #pragma unroll 8
    for (int i = tid; i < NODE_DIM * OUT_DIM; i += THREADS) sWp[i] = Wp[i];
    __syncthreads();

    const int o  = tid & 127;
    const int gp = tid >> 7;   // 0 or 1
    const float bpo = bp[o];

    for (int pi = 0; pi < FIN_GRAPHS / 2; ++pi) {
        int g = blockIdx.x * FIN_GRAPHS + pi * 2 + gp;
        const float* srow = g_S + (size_t)g * NODE_DIM;
        float acc = g_cnt[g] * bpo;
        #pragma unroll 8
        for (int d = 0; d < NODE_DIM; ++d)
            acc = fmaf(__ldg(&srow[d]), sWp[d * OUT_DIM + o], acc);
        out[(size_t)g * OUT_DIM + o] = acc;
    }
}

// ---------------------------------------------------------------------------
extern "C" void kernel_launch(void* const* d_in, const int* in_sizes, int n_in,
                              void* d_out, int out_size)
{
    const float* h_nodes = (const float*)d_in[0];
    const void*  batch   = d_in[1];
    const float* Wg1     = (const float*)d_in[2];
    const float* bg1     = (const float*)d_in[3];
    const float* Wg2     = (const float*)d_in[4];
    const float* bg2     = (const float*)d_in[5];
    const float* Wp      = (const float*)d_in[6];
    const float* bp      = (const float*)d_in[7];
    float* out = (float*)d_out;

    const int N = in_sizes[0] / NODE_DIM;   // number of nodes

    const int fused_smem = (CHUNK * H_STRIDE + NODE_DIM * GATE_HID + GATE_HID
                            + GATE_HID + CHUNK * 8 + CHUNK) * 4 + CHUNK * 4;
    const int final_smem = NODE_DIM * OUT_DIM * 4;

    cudaFuncSetAttribute(fused_kernel, cudaFuncAttributeMaxDynamicSharedMemorySize, fused_smem);
    cudaFuncSetAttribute(final_kernel, cudaFuncAttributeMaxDynamicSharedMemorySize, final_smem);

    // 1) zero scratch
    {
        int total = NUM_GRAPHS * OUT_DIM;
        zero_kernel<<<(total + THREADS - 1) / THREADS, THREADS>>>();
    }
    // 2) fused per-node pass
    {
        int blocks = (N + CHUNK - 1) / CHUNK;
        fused_kernel<<<blocks, THREADS, fused_smem>>>(h_nodes, batch, Wg1, bg1, Wg2, bg2, N);
    }
    // 3) tiny final GEMM + bias
    {
        final_kernel<<<NUM_GRAPHS / FIN_GRAPHS, THREADS, final_smem>>>(Wp, bp, out);
    }
}

// round 4
// speedup vs baseline: 1.5278x; 1.5278x over previous
#include <cuda_runtime.h>
#include <cuda_bf16.h>
#include <stdint.h>

#define NODE_DIM   128
#define GATE_HID   64
#define OUT_DIM    128
#define NUM_GRAPHS 16384
#define CHUNK      128
#define THREADS    256

// padded bf16 row stride: 136 bf16 = 272 bytes (68 words, 68 mod 32 = 4 ->
// the 8x4 fragment-load pattern (4*g + quad) hits all 32 banks, conflict-free)
#define A_STRIDE_B 272

// Scratch: per-graph sum of g*h [B,128] and per-graph sum of g [B]
__device__ float g_S[NUM_GRAPHS * OUT_DIM];
__device__ float g_cnt[NUM_GRAPHS];

// ---------------------------------------------------------------------------
// Warp-level bf16 MMA (legacy tensor path; valid on plain sm_103 target)
// D[16,8] += A[16,16] * B[16,8], fp32 accumulate
// ---------------------------------------------------------------------------
static __device__ __forceinline__ void mma16816(
    float* d, uint32_t a0, uint32_t a1, uint32_t a2, uint32_t a3,
    uint32_t b0, uint32_t b1)
{
    asm volatile(
        "mma.sync.aligned.m16n8k16.row.col.f32.bf16.bf16.f32 "
        "{%0,%1,%2,%3}, {%4,%5,%6,%7}, {%8,%9}, {%0,%1,%2,%3};"
        : "+f"(d[0]), "+f"(d[1]), "+f"(d[2]), "+f"(d[3])
        : "r"(a0), "r"(a1), "r"(a2), "r"(a3), "r"(b0), "r"(b1));
}

// batch may be int32 or int64: int32 view of index N-1 is the zero high word
// under int64 layout, the last (~16383) sorted id under int32 layout.
static __device__ __forceinline__ int batch_at(const void* p, int i, bool is64) {
    if (is64) return (int)(((const long long*)p)[i]);
    return ((const int*)p)[i];
}

// ---------------------------------------------------------------------------
__global__ void zero_kernel() {
    int idx = blockIdx.x * blockDim.x + threadIdx.x;
    if (idx < NUM_GRAPHS * OUT_DIM) g_S[idx] = 0.0f;
    if (idx < NUM_GRAPHS)           g_cnt[idx] = 0.0f;
}

// ---------------------------------------------------------------------------
// Fused pass per 128-node chunk:
//  1) load h tile, split fp32 -> bf16 (hi, lo) into padded smem tiles
//  2) hidden = H_hi*W_hi + H_lo*W_hi + H_hi*W_lo via mma.sync (fp32 acc)
//  3) gate = sigmoid(relu(hidden+b1) . w2 + b2)  in-fragment + shfl reduce
//  4) segment-accumulate S[b] += g*(hi+lo), cnt[b] += g  (sorted batch)
// ---------------------------------------------------------------------------
__global__ __launch_bounds__(THREADS, 2)
void fused_kernel(const float* __restrict__ h_nodes,
                  const void*  __restrict__ batch,
                  const float* __restrict__ Wg1,
                  const float* __restrict__ bg1,
                  const float* __restrict__ Wg2,
                  const float* __restrict__ bg2,
                  int N)
{
    extern __shared__ char sm[];
    char*  smA_hi = sm;                         // 128*272 = 34816
    char*  smA_lo = sm + 34816;                 // 34816
    char*  smB_hi = sm + 69632;                 // 64*272 = 17408
    char*  smB_lo = sm + 87040;                 // 17408
    float* sh_gate = (float*)(sm + 104448);     // 512
    int*   sh_b    = (int*)  (sm + 104960);     // 512
    float* sh_w2   = (float*)(sm + 105472);     // 256
    float* sh_b1   = (float*)(sm + 105728);     // 256

    const int tid  = threadIdx.x;
    const int wid  = tid >> 5;
    const int lane = tid & 31;
    const int gq   = lane >> 2;   // fragment row group 0..7
    const int tq   = lane & 3;    // fragment quad 0..3
    const int base = blockIdx.x * CHUNK;
    const int nn   = min(CHUNK, N - base);

    const bool is64 = (((const int*)batch)[N - 1] == 0);

    // --- stage + convert A (h tile): fp32 -> bf16 hi/lo
    for (int i = tid; i < CHUNK * 32; i += THREADS) {
        int n = i >> 5, q = i & 31;
        float4 v = make_float4(0.f, 0.f, 0.f, 0.f);
        if (n < nn) v = ((const float4*)h_nodes)[(size_t)(base + n) * 32 + q];
        __nv_bfloat16 h0 = __float2bfloat16_rn(v.x);
        __nv_bfloat16 h1 = __float2bfloat16_rn(v.y);
        __nv_bfloat16 h2 = __float2bfloat16_rn(v.z);
        __nv_bfloat16 h3 = __float2bfloat16_rn(v.w);
        __nv_bfloat16 l0 = __float2bfloat16_rn(v.x - __bfloat162float(h0));
        __nv_bfloat16 l1 = __float2bfloat16_rn(v.y - __bfloat162float(h1));
        __nv_bfloat16 l2 = __float2bfloat16_rn(v.z - __bfloat162float(h2));
        __nv_bfloat16 l3 = __float2bfloat16_rn(v.w - __bfloat162float(h3));
        uint32_t off = (uint32_t)n * A_STRIDE_B + (uint32_t)q * 8;
        *(__nv_bfloat162*)(smA_hi + off)     = __nv_bfloat162(h0, h1);
        *(__nv_bfloat162*)(smA_hi + off + 4) = __nv_bfloat162(h2, h3);
        *(__nv_bfloat162*)(smA_lo + off)     = __nv_bfloat162(l0, l1);
        *(__nv_bfloat162*)(smA_lo + off + 4) = __nv_bfloat162(l2, l3);
    }

    // --- stage + convert B = Wg1^T as [n][k]: B[n][k] = Wg1[k*64+n]
    for (int idx = tid; idx < NODE_DIM * GATE_HID; idx += THREADS) {
        int k = idx >> 6, n = idx & 63;
        float w = Wg1[idx];
        __nv_bfloat16 whi = __float2bfloat16_rn(w);
        __nv_bfloat16 wlo = __float2bfloat16_rn(w - __bfloat162float(whi));
        uint32_t off = (uint32_t)n * A_STRIDE_B + (uint32_t)k * 2;
        *(__nv_bfloat16*)(smB_hi + off) = whi;
        *(__nv_bfloat16*)(smB_lo + off) = wlo;
    }

    if (tid < GATE_HID) { sh_w2[tid] = Wg2[tid]; sh_b1[tid] = bg1[tid]; }
    if (tid < CHUNK) sh_b[tid] = (tid < nn) ? batch_at(batch, base + tid, is64) : 0;
    __syncthreads();

    // --- MMA: each warp computes rows [wid*16, wid*16+16) x 64 cols, K=128
    float d[8][4];
    #pragma unroll
    for (int nt = 0; nt < 8; ++nt)
        #pragma unroll
        for (int j = 0; j < 4; ++j) d[nt][j] = 0.0f;

    const char* Ah = smA_hi + (wid * 16 + gq) * A_STRIDE_B;
    const char* Al = smA_lo + (wid * 16 + gq) * A_STRIDE_B;

    #pragma unroll
    for (int ks = 0; ks < 8; ++ks) {
        const int kb = ks * 16 + tq * 2;   // bf16 col index
        uint32_t ah0 = *(const uint32_t*)(Ah + kb * 2);
        uint32_t ah1 = *(const uint32_t*)(Ah + 8 * A_STRIDE_B + kb * 2);
        uint32_t ah2 = *(const uint32_t*)(Ah + (kb + 8) * 2);
        uint32_t ah3 = *(const uint32_t*)(Ah + 8 * A_STRIDE_B + (kb + 8) * 2);
        uint32_t al0 = *(const uint32_t*)(Al + kb * 2);
        uint32_t al1 = *(const uint32_t*)(Al + 8 * A_STRIDE_B + kb * 2);
        uint32_t al2 = *(const uint32_t*)(Al + (kb + 8) * 2);
        uint32_t al3 = *(const uint32_t*)(Al + 8 * A_STRIDE_B + (kb + 8) * 2);
        #pragma unroll
        for (int nt = 0; nt < 8; ++nt) {
            const char* Bh = smB_hi + (nt * 8 + gq) * A_STRIDE_B;
            const char* Bl = smB_lo + (nt * 8 + gq) * A_STRIDE_B;
            uint32_t bh0 = *(const uint32_t*)(Bh + kb * 2);
            uint32_t bh1 = *(const uint32_t*)(Bh + (kb + 8) * 2);
            uint32_t bl0 = *(const uint32_t*)(Bl + kb * 2);
            uint32_t bl1 = *(const uint32_t*)(Bl + (kb + 8) * 2);
            mma16816(d[nt], ah0, ah1, ah2, ah3, bh0, bh1);
            mma16816(d[nt], al0, al1, al2, al3, bh0, bh1);
            mma16816(d[nt], ah0, ah1, ah2, ah3, bl0, bl1);
        }
    }

    // --- gate epilogue in fragments:
    // d[nt][0]: row gq,   col nt*8+tq*2      d[nt][1]: row gq,   col +1
    // d[nt][2]: row gq+8, col nt*8+tq*2      d[nt][3]: row gq+8, col +1
    {
        float s0 = 0.0f, s1 = 0.0f;
        #pragma unroll
        for (int nt = 0; nt < 8; ++nt) {
            int c0 = nt * 8 + tq * 2;
            float b1a = sh_b1[c0], b1b = sh_b1[c0 + 1];
            float w2a = sh_w2[c0], w2b = sh_w2[c0 + 1];
            s0 = fmaf(fmaxf(d[nt][0] + b1a, 0.0f), w2a, s0);
            s0 = fmaf(fmaxf(d[nt][1] + b1b, 0.0f), w2b, s0);
            s1 = fmaf(fmaxf(d[nt][2] + b1a, 0.0f), w2a, s1);
            s1 = fmaf(fmaxf(d[nt][3] + b1b, 0.0f), w2b, s1);
        }
        s0 += __shfl_xor_sync(0xffffffffu, s0, 1);
        s0 += __shfl_xor_sync(0xffffffffu, s0, 2);
        s1 += __shfl_xor_sync(0xffffffffu, s1, 1);
        s1 += __shfl_xor_sync(0xffffffffu, s1, 2);
        if (tq == 0) {
            float b2 = bg2[0];
            sh_gate[wid * 16 + gq]     = 1.0f / (1.0f + __expf(-(s0 + b2)));
            sh_gate[wid * 16 + gq + 8] = 1.0f / (1.0f + __expf(-(s1 + b2)));
        }
    }
    __syncthreads();

    // --- segment accumulate (sorted batch): register acc, flush on change
    {
        const int half = tid >> 7;          // 0 or 1
        const int dd   = tid & 127;
        const int ns   = half * 64;
        const int ne   = min(ns + 64, nn);
        if (ns < ne) {
            int   cur  = sh_b[ns];
            float accS = 0.0f, accG = 0.0f;
            for (int n = ns; n < ne; ++n) {
                int b = sh_b[n];
                if (b != cur) {
                    atomicAdd(&g_S[(size_t)cur * OUT_DIM + dd], accS);
                    if (dd == 0) atomicAdd(&g_cnt[cur], accG);
                    accS = 0.0f; accG = 0.0f; cur = b;
                }
                uint32_t off = (uint32_t)n * A_STRIDE_B + (uint32_t)dd * 2;
                float hv = __bfloat162float(*(__nv_bfloat16*)(smA_hi + off))
                         + __bfloat162float(*(__nv_bfloat16*)(smA_lo + off));
                float g = sh_gate[n];
                accS = fmaf(g, hv, accS);
                if (dd == 0) accG += g;
            }
            atomicAdd(&g_S[(size_t)cur * OUT_DIM + dd], accS);
            if (dd == 0) atomicAdd(&g_cnt[cur], accG);
        }
    }
}

// ---------------------------------------------------------------------------
// Final: out[b] = S[b] @ W_p + cnt[b] * b_p
// ---------------------------------------------------------------------------
#define FIN_GRAPHS 64

__global__ __launch_bounds__(THREADS, 1)
void final_kernel(const float* __restrict__ Wp,
                  const float* __restrict__ bp,
                  float* __restrict__ out)
{
    extern __shared__ float sWp[];   // 128*128 fp32 = 64KB
    const int tid = threadIdx.x;
    #pragma unroll 8
    for (int i = tid; i < NODE_DIM * OUT_DIM; i += THREADS) sWp[i] = Wp[i];
    __syncthreads();

    const int o  = tid & 127;
    const int gp = tid >> 7;
    const float bpo = bp[o];

    for (int pi = 0; pi < FIN_GRAPHS / 2; ++pi) {
        int g = blockIdx.x * FIN_GRAPHS + pi * 2 + gp;
        const float* srow = g_S + (size_t)g * NODE_DIM;
        float acc = g_cnt[g] * bpo;
        #pragma unroll 8
        for (int d = 0; d < NODE_DIM; ++d)
            acc = fmaf(__ldg(&srow[d]), sWp[d * OUT_DIM + o], acc);
        out[(size_t)g * OUT_DIM + o] = acc;
    }
}

// ---------------------------------------------------------------------------
extern "C" void kernel_launch(void* const* d_in, const int* in_sizes, int n_in,
                              void* d_out, int out_size)
{
    const float* h_nodes = (const float*)d_in[0];
    const void*  batch   = d_in[1];
    const float* Wg1     = (const float*)d_in[2];
    const float* bg1     = (const float*)d_in[3];
    const float* Wg2     = (const float*)d_in[4];
    const float* bg2     = (const float*)d_in[5];
    const float* Wp      = (const float*)d_in[6];
    const float* bp      = (const float*)d_in[7];
    float* out = (float*)d_out;

    const int N = in_sizes[0] / NODE_DIM;

    const int fused_smem = 105984;                 // see smem map above
    const int final_smem = NODE_DIM * OUT_DIM * 4; // 64KB

    cudaFuncSetAttribute(fused_kernel, cudaFuncAttributeMaxDynamicSharedMemorySize, fused_smem);
    cudaFuncSetAttribute(final_kernel, cudaFuncAttributeMaxDynamicSharedMemorySize, final_smem);

    {
        int total = NUM_GRAPHS * OUT_DIM;
        zero_kernel<<<(total + THREADS - 1) / THREADS, THREADS>>>();
    }
    {
        int blocks = (N + CHUNK - 1) / CHUNK;
        fused_kernel<<<blocks, THREADS, fused_smem>>>(h_nodes, batch, Wg1, bg1, Wg2, bg2, N);
    }
    {
        final_kernel<<<NUM_GRAPHS / FIN_GRAPHS, THREADS, final_smem>>>(Wp, bp, out);
    }
}

// round 6
// speedup vs baseline: 1.6880x; 1.1049x over previous
#include <cuda_runtime.h>
#include <cuda_fp16.h>
#include <stdint.h>

#define NODE_DIM   128
#define GATE_HID   64
#define OUT_DIM    128
#define NUM_GRAPHS 16384
#define CHUNK      128
#define THREADS    256

// padded fp16 row stride: 136 halves = 272 bytes (68 words; 68 mod 32 = 4 ->
// the 8x4 fragment-load pattern hits all 32 banks, conflict-free)
#define A_STRIDE_B 272

// Scratch: per-graph sum of g*h [B,128] and per-graph sum of g [B]
__device__ float g_S[NUM_GRAPHS * OUT_DIM];
__device__ float g_cnt[NUM_GRAPHS];

// reinterpret __half2 bits as u32 (no standard intrinsic for this)
static __device__ __forceinline__ uint32_t u32_of(__half2 h) {
    union { __half2 h; uint32_t u; } c; c.h = h; return c.u;
}

// ---------------------------------------------------------------------------
// Warp-level fp16 MMA: D[16,8] += A[16,16] * B[16,8], fp32 accumulate
// ---------------------------------------------------------------------------
static __device__ __forceinline__ void mma16816(
    float* d, uint32_t a0, uint32_t a1, uint32_t a2, uint32_t a3,
    uint32_t b0, uint32_t b1)
{
    asm volatile(
        "mma.sync.aligned.m16n8k16.row.col.f32.f16.f16.f32 "
        "{%0,%1,%2,%3}, {%4,%5,%6,%7}, {%8,%9}, {%0,%1,%2,%3};"
        : "+f"(d[0]), "+f"(d[1]), "+f"(d[2]), "+f"(d[3])
        : "r"(a0), "r"(a1), "r"(a2), "r"(a3), "r"(b0), "r"(b1));
}

// batch may be int32 or int64: int32 view of index N-1 is the zero high word
// under int64 layout, the last (~16383) sorted id under int32 layout.
static __device__ __forceinline__ int batch_at(const void* p, int i, bool is64) {
    if (is64) return (int)(((const long long*)p)[i]);
    return ((const int*)p)[i];
}

// ---------------------------------------------------------------------------
__global__ void zero_kernel() {
    int idx = blockIdx.x * blockDim.x + threadIdx.x;
    if (idx < NUM_GRAPHS * OUT_DIM) g_S[idx] = 0.0f;
    if (idx < NUM_GRAPHS)           g_cnt[idx] = 0.0f;
}

// ---------------------------------------------------------------------------
// Fused pass per 128-node chunk:
//  1) load h tile, split fp32 -> fp16 (hi, lo); W -> single fp16 RN
//  2) hidden = H_hi*W + H_lo*W  via mma.sync (fp32 acc); error ~2^-11 on W only
//  3) gate = sigmoid(relu(hidden+b1) . w2 + b2)  in-fragment + shfl reduce
//  4) segment-accumulate S[b] += g*(hi+lo), cnt[b] += g  (sorted batch)
// ---------------------------------------------------------------------------
__global__ __launch_bounds__(THREADS, 2)
void fused_kernel(const float* __restrict__ h_nodes,
                  const void*  __restrict__ batch,
                  const float* __restrict__ Wg1,
                  const float* __restrict__ bg1,
                  const float* __restrict__ Wg2,
                  const float* __restrict__ bg2,
                  int N)
{
    extern __shared__ char sm[];
    char*  smA_hi  = sm;                        // 128*272 = 34816
    char*  smA_lo  = sm + 34816;                // 34816
    char*  smB     = sm + 69632;                // 64*272 = 17408
    float* sh_gate = (float*)(sm + 87040);      // 512
    int*   sh_b    = (int*)  (sm + 87552);      // 512
    float* sh_w2   = (float*)(sm + 88064);      // 256
    float* sh_b1   = (float*)(sm + 88320);      // 256
                                                // total 88576

    const int tid  = threadIdx.x;
    const int wid  = tid >> 5;
    const int lane = tid & 31;
    const int gq   = lane >> 2;   // fragment row group 0..7
    const int tq   = lane & 3;    // fragment quad 0..3
    const int base = blockIdx.x * CHUNK;
    const int nn   = min(CHUNK, N - base);

    const bool is64 = (((const int*)batch)[N - 1] == 0);

    // --- stage + convert A (h tile): fp32 -> fp16 hi/lo, packed cvt
    for (int i = tid; i < CHUNK * 32; i += THREADS) {
        int n = i >> 5, q = i & 31;
        float4 v = make_float4(0.f, 0.f, 0.f, 0.f);
        if (n < nn) v = ((const float4*)h_nodes)[(size_t)(base + n) * 32 + q];
        __half2 h01 = __floats2half2_rn(v.x, v.y);
        __half2 h23 = __floats2half2_rn(v.z, v.w);
        float2 f01 = __half22float2(h01);
        float2 f23 = __half22float2(h23);
        __half2 l01 = __floats2half2_rn(v.x - f01.x, v.y - f01.y);
        __half2 l23 = __floats2half2_rn(v.z - f23.x, v.w - f23.y);
        uint32_t off = (uint32_t)n * A_STRIDE_B + (uint32_t)q * 8;
        *(uint2*)(smA_hi + off) = make_uint2(u32_of(h01), u32_of(h23));
        *(uint2*)(smA_lo + off) = make_uint2(u32_of(l01), u32_of(l23));
    }

    // --- stage + convert B = Wg1^T as [n][k]: B[n][k] = Wg1[k*64+n], fp16 RN
    for (int idx = tid; idx < NODE_DIM * GATE_HID; idx += THREADS) {
        int k = idx >> 6, n = idx & 63;
        __half w = __float2half_rn(Wg1[idx]);
        *(__half*)(smB + (uint32_t)n * A_STRIDE_B + (uint32_t)k * 2) = w;
    }

    if (tid < GATE_HID) { sh_w2[tid] = Wg2[tid]; sh_b1[tid] = bg1[tid]; }
    if (tid < CHUNK) sh_b[tid] = (tid < nn) ? batch_at(batch, base + tid, is64) : 0;
    __syncthreads();

    // --- MMA: each warp computes rows [wid*16, wid*16+16) x 64 cols, K=128
    float d[8][4];
    #pragma unroll
    for (int nt = 0; nt < 8; ++nt)
        #pragma unroll
        for (int j = 0; j < 4; ++j) d[nt][j] = 0.0f;

    const char* Ah = smA_hi + (wid * 16 + gq) * A_STRIDE_B;
    const char* Al = smA_lo + (wid * 16 + gq) * A_STRIDE_B;

    #pragma unroll
    for (int ks = 0; ks < 8; ++ks) {
        const int kb = ks * 16 + tq * 2;   // fp16 col index
        uint32_t ah0 = *(const uint32_t*)(Ah + kb * 2);
        uint32_t ah1 = *(const uint32_t*)(Ah + 8 * A_STRIDE_B + kb * 2);
        uint32_t ah2 = *(const uint32_t*)(Ah + (kb + 8) * 2);
        uint32_t ah3 = *(const uint32_t*)(Ah + 8 * A_STRIDE_B + (kb + 8) * 2);
        uint32_t al0 = *(const uint32_t*)(Al + kb * 2);
        uint32_t al1 = *(const uint32_t*)(Al + 8 * A_STRIDE_B + kb * 2);
        uint32_t al2 = *(const uint32_t*)(Al + (kb + 8) * 2);
        uint32_t al3 = *(const uint32_t*)(Al + 8 * A_STRIDE_B + (kb + 8) * 2);
        #pragma unroll
        for (int nt = 0; nt < 8; ++nt) {
            const char* Bp = smB + (nt * 8 + gq) * A_STRIDE_B;
            uint32_t b0 = *(const uint32_t*)(Bp + kb * 2);
            uint32_t b1 = *(const uint32_t*)(Bp + (kb + 8) * 2);
            mma16816(d[nt], ah0, ah1, ah2, ah3, b0, b1);
            mma16816(d[nt], al0, al1, al2, al3, b0, b1);
        }
    }

    // --- gate epilogue in fragments:
    // d[nt][0]: row gq,   col nt*8+tq*2    d[nt][1]: col +1
    // d[nt][2]: row gq+8, col nt*8+tq*2    d[nt][3]: col +1
    {
        float s0 = 0.0f, s1 = 0.0f;
        #pragma unroll
        for (int nt = 0; nt < 8; ++nt) {
            int c0 = nt * 8 + tq * 2;
            float b1a = sh_b1[c0], b1b = sh_b1[c0 + 1];
            float w2a = sh_w2[c0], w2b = sh_w2[c0 + 1];
            s0 = fmaf(fmaxf(d[nt][0] + b1a, 0.0f), w2a, s0);
            s0 = fmaf(fmaxf(d[nt][1] + b1b, 0.0f), w2b, s0);
            s1 = fmaf(fmaxf(d[nt][2] + b1a, 0.0f), w2a, s1);
            s1 = fmaf(fmaxf(d[nt][3] + b1b, 0.0f), w2b, s1);
        }
        s0 += __shfl_xor_sync(0xffffffffu, s0, 1);
        s0 += __shfl_xor_sync(0xffffffffu, s0, 2);
        s1 += __shfl_xor_sync(0xffffffffu, s1, 1);
        s1 += __shfl_xor_sync(0xffffffffu, s1, 2);
        if (tq == 0) {
            float b2 = bg2[0];
            sh_gate[wid * 16 + gq]     = 1.0f / (1.0f + __expf(-(s0 + b2)));
            sh_gate[wid * 16 + gq + 8] = 1.0f / (1.0f + __expf(-(s1 + b2)));
        }
    }
    __syncthreads();

    // --- segment accumulate (sorted batch): register acc, flush on change
    {
        const int half = tid >> 7;          // 0 or 1
        const int dd   = tid & 127;
        const int ns   = half * 64;
        const int ne   = min(ns + 64, nn);
        if (ns < ne) {
            int   cur  = sh_b[ns];
            float accS = 0.0f, accG = 0.0f;
            for (int n = ns; n < ne; ++n) {
                int b = sh_b[n];
                if (b != cur) {
                    atomicAdd(&g_S[(size_t)cur * OUT_DIM + dd], accS);
                    if (dd == 0) atomicAdd(&g_cnt[cur], accG);
                    accS = 0.0f; accG = 0.0f; cur = b;
                }
                uint32_t off = (uint32_t)n * A_STRIDE_B + (uint32_t)dd * 2;
                float hv = __half2float(*(__half*)(smA_hi + off))
                         + __half2float(*(__half*)(smA_lo + off));
                float g = sh_gate[n];
                accS = fmaf(g, hv, accS);
                if (dd == 0) accG += g;
            }
            atomicAdd(&g_S[(size_t)cur * OUT_DIM + dd], accS);
            if (dd == 0) atomicAdd(&g_cnt[cur], accG);
        }
    }
}

// ---------------------------------------------------------------------------
// Final: out[b] = S[b] @ W_p + cnt[b] * b_p
// ---------------------------------------------------------------------------
#define FIN_GRAPHS 64

__global__ __launch_bounds__(THREADS, 1)
void final_kernel(const float* __restrict__ Wp,
                  const float* __restrict__ bp,
                  float* __restrict__ out)
{
    extern __shared__ float sWp[];   // 128*128 fp32 = 64KB
    const int tid = threadIdx.x;
    #pragma unroll 8
    for (int i = tid; i < NODE_DIM * OUT_DIM; i += THREADS) sWp[i] = Wp[i];
    __syncthreads();

    const int o  = tid & 127;
    const int gp = tid >> 7;
    const float bpo = bp[o];

    for (int pi = 0; pi < FIN_GRAPHS / 2; ++pi) {
        int g = blockIdx.x * FIN_GRAPHS + pi * 2 + gp;
        const float* srow = g_S + (size_t)g * NODE_DIM;
        float acc = g_cnt[g] * bpo;
        #pragma unroll 8
        for (int d = 0; d < NODE_DIM; ++d)
            acc = fmaf(__ldg(&srow[d]), sWp[d * OUT_DIM + o], acc);
        out[(size_t)g * OUT_DIM + o] = acc;
    }
}

// ---------------------------------------------------------------------------
extern "C" void kernel_launch(void* const* d_in, const int* in_sizes, int n_in,
                              void* d_out, int out_size)
{
    const float* h_nodes = (const float*)d_in[0];
    const void*  batch   = d_in[1];
    const float* Wg1     = (const float*)d_in[2];
    const float* bg1     = (const float*)d_in[3];
    const float* Wg2     = (const float*)d_in[4];
    const float* bg2     = (const float*)d_in[5];
    const float* Wp      = (const float*)d_in[6];
    const float* bp      = (const float*)d_in[7];
    float* out = (float*)d_out;

    const int N = in_sizes[0] / NODE_DIM;

    const int fused_smem = 88576;                  // see smem map above
    const int final_smem = NODE_DIM * OUT_DIM * 4; // 64KB

    cudaFuncSetAttribute(fused_kernel, cudaFuncAttributeMaxDynamicSharedMemorySize, fused_smem);
    cudaFuncSetAttribute(final_kernel, cudaFuncAttributeMaxDynamicSharedMemorySize, final_smem);

    {
        int total = NUM_GRAPHS * OUT_DIM;
        zero_kernel<<<(total + THREADS - 1) / THREADS, THREADS>>>();
    }
    {
        int blocks = (N + CHUNK - 1) / CHUNK;
        fused_kernel<<<blocks, THREADS, fused_smem>>>(h_nodes, batch, Wg1, bg1, Wg2, bg2, N);
    }
    {
        final_kernel<<<NUM_GRAPHS / FIN_GRAPHS, THREADS, final_smem>>>(Wp, bp, out);
    }
}

// round 7
// speedup vs baseline: 2.4223x; 1.4350x over previous
#include <cuda_runtime.h>
#include <cuda_fp16.h>
#include <stdint.h>

#define NODE_DIM   128
#define GATE_HID   64
#define OUT_DIM    128
#define NUM_GRAPHS 16384
#define CHUNK      128
#define THREADS    256

// padded fp16 row stride: 136 halves = 272 bytes (68 words; 68 mod 32 = 4 ->
// the 8x4 fragment-load pattern hits all 32 banks, conflict-free)
#define A_STRIDE_B 272

// Scratch: per-graph sum of g*h [B,128] and per-graph sum of g [B].
// Invariant: zero at kernel_launch entry. Loader zero-init covers call #1;
// final_kernel re-zeros its exclusive slice after consuming it.
__device__ float g_S[NUM_GRAPHS * OUT_DIM];
__device__ float g_cnt[NUM_GRAPHS];

// reinterpret __half2 bits as u32
static __device__ __forceinline__ uint32_t u32_of(__half2 h) {
    union { __half2 h; uint32_t u; } c; c.h = h; return c.u;
}

// ---------------------------------------------------------------------------
// Warp-level fp16 MMA: D[16,8] += A[16,16] * B[16,8], fp32 accumulate
// ---------------------------------------------------------------------------
static __device__ __forceinline__ void mma16816(
    float* d, uint32_t a0, uint32_t a1, uint32_t a2, uint32_t a3,
    uint32_t b0, uint32_t b1)
{
    asm volatile(
        "mma.sync.aligned.m16n8k16.row.col.f32.f16.f16.f32 "
        "{%0,%1,%2,%3}, {%4,%5,%6,%7}, {%8,%9}, {%0,%1,%2,%3};"
        : "+f"(d[0]), "+f"(d[1]), "+f"(d[2]), "+f"(d[3])
        : "r"(a0), "r"(a1), "r"(a2), "r"(a3), "r"(b0), "r"(b1));
}

// batch may be int32 or int64: int32 view of index N-1 (odd) is the zero high
// word under int64 layout, the last (~16383) sorted id under int32 layout.
static __device__ __forceinline__ int batch_at(const void* p, int i, bool is64) {
    if (is64) return (int)(((const long long*)p)[i]);
    return ((const int*)p)[i];
}

// ---------------------------------------------------------------------------
// Fused pass per 128-node chunk:
//  1) load h tile (fp32), convert to single RN fp16 tile in smem
//  2) hidden = H*W via mma.sync fp32-acc (single pass)
//  3) gate = sigmoid(relu(hidden+b1) . w2 + b2)  in-fragment + shfl reduce
//  4) segment-accumulate S[b] += g*h (exact fp32 h re-read from global, L1-hot)
// ---------------------------------------------------------------------------
__global__ __launch_bounds__(THREADS, 3)
void fused_kernel(const float* __restrict__ h_nodes,
                  const void*  __restrict__ batch,
                  const float* __restrict__ Wg1,
                  const float* __restrict__ bg1,
                  const float* __restrict__ Wg2,
                  const float* __restrict__ bg2,
                  int N)
{
    extern __shared__ char sm[];
    char*  smA     = sm;                        // 128*272 = 34816
    char*  smB     = sm + 34816;                // 64*272 = 17408
    float* sh_gate = (float*)(sm + 52224);      // 512
    int*   sh_b    = (int*)  (sm + 52736);      // 512
    float* sh_w2   = (float*)(sm + 53248);      // 256
    float* sh_b1   = (float*)(sm + 53504);      // 256
                                                // total 53760

    const int tid  = threadIdx.x;
    const int wid  = tid >> 5;
    const int lane = tid & 31;
    const int gq   = lane >> 2;   // fragment row group 0..7
    const int tq   = lane & 3;    // fragment quad 0..3
    const int base = blockIdx.x * CHUNK;
    const int nn   = min(CHUNK, N - base);

    const bool is64 = (((const int*)batch)[N - 1] == 0);

    // --- stage + convert A (h tile): fp32 -> single fp16 RN
    #pragma unroll 4
    for (int i = tid; i < CHUNK * 32; i += THREADS) {
        int n = i >> 5, q = i & 31;
        float4 v = make_float4(0.f, 0.f, 0.f, 0.f);
        if (n < nn) v = ((const float4*)h_nodes)[(size_t)(base + n) * 32 + q];
        __half2 h01 = __floats2half2_rn(v.x, v.y);
        __half2 h23 = __floats2half2_rn(v.z, v.w);
        *(uint2*)(smA + (uint32_t)n * A_STRIDE_B + (uint32_t)q * 8) =
            make_uint2(u32_of(h01), u32_of(h23));
    }

    // --- stage + convert B = Wg1^T as [n][k]: B[n][k] = Wg1[k*64+n], fp16 RN
    #pragma unroll 4
    for (int idx = tid; idx < NODE_DIM * GATE_HID; idx += THREADS) {
        int k = idx >> 6, n = idx & 63;
        __half w = __float2half_rn(Wg1[idx]);
        *(__half*)(smB + (uint32_t)n * A_STRIDE_B + (uint32_t)k * 2) = w;
    }

    if (tid < GATE_HID) { sh_w2[tid] = Wg2[tid]; sh_b1[tid] = bg1[tid]; }
    if (tid < CHUNK) sh_b[tid] = (tid < nn) ? batch_at(batch, base + tid, is64) : 0;
    __syncthreads();

    // --- MMA: each warp computes rows [wid*16, wid*16+16) x 64 cols, K=128
    float d[8][4];
    #pragma unroll
    for (int nt = 0; nt < 8; ++nt)
        #pragma unroll
        for (int j = 0; j < 4; ++j) d[nt][j] = 0.0f;

    const char* Ah = smA + (wid * 16 + gq) * A_STRIDE_B;

    #pragma unroll
    for (int ks = 0; ks < 8; ++ks) {
        const int kb = ks * 16 + tq * 2;   // fp16 col index
        uint32_t a0 = *(const uint32_t*)(Ah + kb * 2);
        uint32_t a1 = *(const uint32_t*)(Ah + 8 * A_STRIDE_B + kb * 2);
        uint32_t a2 = *(const uint32_t*)(Ah + (kb + 8) * 2);
        uint32_t a3 = *(const uint32_t*)(Ah + 8 * A_STRIDE_B + (kb + 8) * 2);
        #pragma unroll
        for (int nt = 0; nt < 8; ++nt) {
            const char* Bp = smB + (nt * 8 + gq) * A_STRIDE_B;
            uint32_t b0 = *(const uint32_t*)(Bp + kb * 2);
            uint32_t b1 = *(const uint32_t*)(Bp + (kb + 8) * 2);
            mma16816(d[nt], a0, a1, a2, a3, b0, b1);
        }
    }

    // --- gate epilogue in fragments:
    // d[nt][0]: row gq,   col nt*8+tq*2    d[nt][1]: col +1
    // d[nt][2]: row gq+8, col nt*8+tq*2    d[nt][3]: col +1
    {
        float s0 = 0.0f, s1 = 0.0f;
        #pragma unroll
        for (int nt = 0; nt < 8; ++nt) {
            int c0 = nt * 8 + tq * 2;
            float b1a = sh_b1[c0], b1b = sh_b1[c0 + 1];
            float w2a = sh_w2[c0], w2b = sh_w2[c0 + 1];
            s0 = fmaf(fmaxf(d[nt][0] + b1a, 0.0f), w2a, s0);
            s0 = fmaf(fmaxf(d[nt][1] + b1b, 0.0f), w2b, s0);
            s1 = fmaf(fmaxf(d[nt][2] + b1a, 0.0f), w2a, s1);
            s1 = fmaf(fmaxf(d[nt][3] + b1b, 0.0f), w2b, s1);
        }
        s0 += __shfl_xor_sync(0xffffffffu, s0, 1);
        s0 += __shfl_xor_sync(0xffffffffu, s0, 2);
        s1 += __shfl_xor_sync(0xffffffffu, s1, 1);
        s1 += __shfl_xor_sync(0xffffffffu, s1, 2);
        if (tq == 0) {
            float b2 = bg2[0];
            sh_gate[wid * 16 + gq]     = 1.0f / (1.0f + __expf(-(s0 + b2)));
            sh_gate[wid * 16 + gq + 8] = 1.0f / (1.0f + __expf(-(s1 + b2)));
        }
    }
    __syncthreads();

    // --- segment accumulate (sorted batch): register acc, flush on change.
    // h is re-read from global (exact fp32; tile is L1/L2-hot from stage 1).
    {
        const int half = tid >> 7;          // 0 or 1
        const int dd   = tid & 127;
        const int ns   = half * 64;
        const int ne   = min(ns + 64, nn);
        if (ns < ne) {
            const float* hcol = h_nodes + (size_t)base * NODE_DIM + dd;
            int   cur  = sh_b[ns];
            float accS = 0.0f, accG = 0.0f;
            for (int n = ns; n < ne; ++n) {
                int b = sh_b[n];
                if (b != cur) {
                    atomicAdd(&g_S[(size_t)cur * OUT_DIM + dd], accS);
                    if (dd == 0) atomicAdd(&g_cnt[cur], accG);
                    accS = 0.0f; accG = 0.0f; cur = b;
                }
                float hv = __ldg(hcol + (size_t)n * NODE_DIM);
                float g  = sh_gate[n];
                accS = fmaf(g, hv, accS);
                if (dd == 0) accG += g;
            }
            atomicAdd(&g_S[(size_t)cur * OUT_DIM + dd], accS);
            if (dd == 0) atomicAdd(&g_cnt[cur], accG);
        }
    }
}

// ---------------------------------------------------------------------------
// Final: out[b] = S[b] @ W_p + cnt[b] * b_p ; then re-zero this block's
// exclusive slice of g_S/g_cnt (restores the zero-at-entry invariant).
// ---------------------------------------------------------------------------
#define FIN_GRAPHS 64

__global__ __launch_bounds__(THREADS, 1)
void final_kernel(const float* __restrict__ Wp,
                  const float* __restrict__ bp,
                  float* __restrict__ out)
{
    extern __shared__ float sWp[];   // 128*128 fp32 = 64KB
    const int tid = threadIdx.x;
    #pragma unroll 8
    for (int i = tid; i < NODE_DIM * OUT_DIM; i += THREADS) sWp[i] = Wp[i];
    __syncthreads();

    const int o  = tid & 127;
    const int gp = tid >> 7;
    const float bpo = bp[o];

    for (int pi = 0; pi < FIN_GRAPHS / 2; ++pi) {
        int g = blockIdx.x * FIN_GRAPHS + pi * 2 + gp;
        const float* srow = g_S + (size_t)g * NODE_DIM;
        float acc = g_cnt[g] * bpo;
        #pragma unroll 8
        for (int d = 0; d < NODE_DIM; ++d)
            acc = fmaf(__ldg(&srow[d]), sWp[d * OUT_DIM + o], acc);
        out[(size_t)g * OUT_DIM + o] = acc;
    }

    // all reads of this block's slice are done -> re-zero for the next call
    __syncthreads();
    float4 z = make_float4(0.f, 0.f, 0.f, 0.f);
    float4* srow4 = (float4*)(g_S + (size_t)blockIdx.x * FIN_GRAPHS * NODE_DIM);
    #pragma unroll 4
    for (int i = tid; i < FIN_GRAPHS * NODE_DIM / 4; i += THREADS) srow4[i] = z;
    if (tid < FIN_GRAPHS) g_cnt[blockIdx.x * FIN_GRAPHS + tid] = 0.0f;
}

// ---------------------------------------------------------------------------
extern "C" void kernel_launch(void* const* d_in, const int* in_sizes, int n_in,
                              void* d_out, int out_size)
{
    const float* h_nodes = (const float*)d_in[0];
    const void*  batch   = d_in[1];
    const float* Wg1     = (const float*)d_in[2];
    const float* bg1     = (const float*)d_in[3];
    const float* Wg2     = (const float*)d_in[4];
    const float* bg2     = (const float*)d_in[5];
    const float* Wp      = (const float*)d_in[6];
    const float* bp      = (const float*)d_in[7];
    float* out = (float*)d_out;

    const int N = in_sizes[0] / NODE_DIM;

    const int fused_smem = 53760;                  // see smem map above
    const int final_smem = NODE_DIM * OUT_DIM * 4; // 64KB

    cudaFuncSetAttribute(fused_kernel, cudaFuncAttributeMaxDynamicSharedMemorySize, fused_smem);
    cudaFuncSetAttribute(final_kernel, cudaFuncAttributeMaxDynamicSharedMemorySize, final_smem);

    {
        int blocks = (N + CHUNK - 1) / CHUNK;
        fused_kernel<<<blocks, THREADS, fused_smem>>>(h_nodes, batch, Wg1, bg1, Wg2, bg2, N);
    }
    {
        final_kernel<<<NUM_GRAPHS / FIN_GRAPHS, THREADS, final_smem>>>(Wp, bp, out);
    }
}

// round 8
// speedup vs baseline: 3.8363x; 1.5838x over previous
#include <cuda_runtime.h>
#include <cuda_fp16.h>
#include <stdint.h>

#define NODE_DIM   128
#define GATE_HID   64
#define OUT_DIM    128
#define NUM_GRAPHS 16384
#define CHUNK      128
#define THREADS    256

// padded fp16 row stride: 136 halves = 272 bytes (68 words; 68 mod 32 = 4 ->
// the 8x4 fragment-load pattern hits all 32 banks, conflict-free)
#define A_STRIDE_B 272
#define B_STRIDE_H 136   // halves

// Scratch: per-graph sum of g*h [B,128] and per-graph sum of g [B].
// Invariant: zero at kernel_launch entry. Loader zero-init covers call #1;
// final_kernel re-zeros its exclusive slice after consuming it.
__device__ float g_S[NUM_GRAPHS * OUT_DIM];
__device__ float g_cnt[NUM_GRAPHS];
// Pre-converted fp16 Wg1^T in the exact MMA smem layout (64 rows x 136 stride)
__device__ __half g_B16[GATE_HID * B_STRIDE_H];

// reinterpret __half2 bits as u32
static __device__ __forceinline__ uint32_t u32_of(__half2 h) {
    union { __half2 h; uint32_t u; } c; c.h = h; return c.u;
}

// ---------------------------------------------------------------------------
// Warp-level fp16 MMA: D[16,8] += A[16,16] * B[16,8], fp32 accumulate
// ---------------------------------------------------------------------------
static __device__ __forceinline__ void mma16816(
    float* d, uint32_t a0, uint32_t a1, uint32_t a2, uint32_t a3,
    uint32_t b0, uint32_t b1)
{
    asm volatile(
        "mma.sync.aligned.m16n8k16.row.col.f32.f16.f16.f32 "
        "{%0,%1,%2,%3}, {%4,%5,%6,%7}, {%8,%9}, {%0,%1,%2,%3};"
        : "+f"(d[0]), "+f"(d[1]), "+f"(d[2]), "+f"(d[3])
        : "r"(a0), "r"(a1), "r"(a2), "r"(a3), "r"(b0), "r"(b1));
}

// batch may be int32 or int64: int32 view of index N-1 (odd) is the zero high
// word under int64 layout, the last (~16383) sorted id under int32 layout.
static __device__ __forceinline__ int batch_at(const void* p, int i, bool is64) {
    if (is64) return (int)(((const long long*)p)[i]);
    return ((const int*)p)[i];
}

// ---------------------------------------------------------------------------
// prep: convert Wg1 [128,64] -> fp16 B tile [n][k] in padded smem layout
// ---------------------------------------------------------------------------
__global__ void prep_kernel(const float* __restrict__ Wg1) {
    const int tid = threadIdx.x;
    // zero padding region first
    for (int i = tid; i < GATE_HID * B_STRIDE_H / 8; i += THREADS)
        ((uint4*)g_B16)[i] = make_uint4(0, 0, 0, 0);
    __syncthreads();
    for (int idx = tid; idx < NODE_DIM * GATE_HID; idx += THREADS) {
        int k = idx >> 6, n = idx & 63;
        g_B16[n * B_STRIDE_H + k] = __float2half_rn(Wg1[idx]);
    }
}

// ---------------------------------------------------------------------------
// Fused pass per 128-node chunk:
//  1) load h tile (fp32), convert to single RN fp16 tile in smem
//  2) hidden = H*W via mma.sync fp32-acc (B tile pre-converted)
//  3) gate = sigmoid(relu(hidden+b1) . w2 + b2)  in-fragment + shfl reduce
//  4) segment-accumulate S[b] += g*h (exact fp32 h re-read from global, L1-hot)
// ---------------------------------------------------------------------------
__global__ __launch_bounds__(THREADS, 4)
void fused_kernel(const float* __restrict__ h_nodes,
                  const void*  __restrict__ batch,
                  const float* __restrict__ bg1,
                  const float* __restrict__ Wg2,
                  const float* __restrict__ bg2,
                  int N)
{
    extern __shared__ char sm[];
    char*  smA     = sm;                        // 128*272 = 34816
    char*  smB     = sm + 34816;                // 64*272 = 17408
    float* sh_gate = (float*)(sm + 52224);      // 512
    int*   sh_b    = (int*)  (sm + 52736);      // 512
    float* sh_w2   = (float*)(sm + 53248);      // 256
    float* sh_b1   = (float*)(sm + 53504);      // 256
                                                // total 53760

    const int tid  = threadIdx.x;
    const int wid  = tid >> 5;
    const int lane = tid & 31;
    const int gq   = lane >> 2;   // fragment row group 0..7
    const int tq   = lane & 3;    // fragment quad 0..3
    const int base = blockIdx.x * CHUNK;
    const int nn   = min(CHUNK, N - base);

    const bool is64 = (((const int*)batch)[N - 1] == 0);

    // --- stage + convert A (h tile): fp32 -> single fp16 RN
    #pragma unroll 4
    for (int i = tid; i < CHUNK * 32; i += THREADS) {
        int n = i >> 5, q = i & 31;
        float4 v = make_float4(0.f, 0.f, 0.f, 0.f);
        if (n < nn) v = ((const float4*)h_nodes)[(size_t)(base + n) * 32 + q];
        __half2 h01 = __floats2half2_rn(v.x, v.y);
        __half2 h23 = __floats2half2_rn(v.z, v.w);
        *(uint2*)(smA + (uint32_t)n * A_STRIDE_B + (uint32_t)q * 8) =
            make_uint2(u32_of(h01), u32_of(h23));
    }

    // --- copy pre-converted B tile (17408 B = 1088 uint4)
    #pragma unroll 5
    for (int i = tid; i < GATE_HID * B_STRIDE_H / 8; i += THREADS)
        ((uint4*)smB)[i] = ((const uint4*)g_B16)[i];

    if (tid < GATE_HID) { sh_w2[tid] = Wg2[tid]; sh_b1[tid] = bg1[tid]; }
    if (tid < CHUNK) sh_b[tid] = (tid < nn) ? batch_at(batch, base + tid, is64) : 0;
    __syncthreads();

    // --- MMA: each warp computes rows [wid*16, wid*16+16) x 64 cols, K=128
    float d[8][4];
    #pragma unroll
    for (int nt = 0; nt < 8; ++nt)
        #pragma unroll
        for (int j = 0; j < 4; ++j) d[nt][j] = 0.0f;

    const char* Ah = smA + (wid * 16 + gq) * A_STRIDE_B;

    #pragma unroll
    for (int ks = 0; ks < 8; ++ks) {
        const int kb = ks * 16 + tq * 2;   // fp16 col index
        uint32_t a0 = *(const uint32_t*)(Ah + kb * 2);
        uint32_t a1 = *(const uint32_t*)(Ah + 8 * A_STRIDE_B + kb * 2);
        uint32_t a2 = *(const uint32_t*)(Ah + (kb + 8) * 2);
        uint32_t a3 = *(const uint32_t*)(Ah + 8 * A_STRIDE_B + (kb + 8) * 2);
        #pragma unroll
        for (int nt = 0; nt < 8; ++nt) {
            const char* Bp = smB + (nt * 8 + gq) * A_STRIDE_B;
            uint32_t b0 = *(const uint32_t*)(Bp + kb * 2);
            uint32_t b1 = *(const uint32_t*)(Bp + (kb + 8) * 2);
            mma16816(d[nt], a0, a1, a2, a3, b0, b1);
        }
    }

    // --- gate epilogue in fragments
    {
        float s0 = 0.0f, s1 = 0.0f;
        #pragma unroll
        for (int nt = 0; nt < 8; ++nt) {
            int c0 = nt * 8 + tq * 2;
            float b1a = sh_b1[c0], b1b = sh_b1[c0 + 1];
            float w2a = sh_w2[c0], w2b = sh_w2[c0 + 1];
            s0 = fmaf(fmaxf(d[nt][0] + b1a, 0.0f), w2a, s0);
            s0 = fmaf(fmaxf(d[nt][1] + b1b, 0.0f), w2b, s0);
            s1 = fmaf(fmaxf(d[nt][2] + b1a, 0.0f), w2a, s1);
            s1 = fmaf(fmaxf(d[nt][3] + b1b, 0.0f), w2b, s1);
        }
        s0 += __shfl_xor_sync(0xffffffffu, s0, 1);
        s0 += __shfl_xor_sync(0xffffffffu, s0, 2);
        s1 += __shfl_xor_sync(0xffffffffu, s1, 1);
        s1 += __shfl_xor_sync(0xffffffffu, s1, 2);
        if (tq == 0) {
            float b2 = bg2[0];
            sh_gate[wid * 16 + gq]     = 1.0f / (1.0f + __expf(-(s0 + b2)));
            sh_gate[wid * 16 + gq + 8] = 1.0f / (1.0f + __expf(-(s1 + b2)));
        }
    }
    __syncthreads();

    // --- segment accumulate (sorted batch): register acc, flush on change.
    // h is re-read from global (exact fp32; tile is L1/L2-hot from stage 1).
    {
        const int half = tid >> 7;          // 0 or 1
        const int dd   = tid & 127;
        const int ns   = half * 64;
        const int ne   = min(ns + 64, nn);
        if (ns < ne) {
            const float* hcol = h_nodes + (size_t)base * NODE_DIM + dd;
            int   cur  = sh_b[ns];
            float accS = 0.0f, accG = 0.0f;
            for (int n = ns; n < ne; ++n) {
                int b = sh_b[n];
                if (b != cur) {
                    atomicAdd(&g_S[(size_t)cur * OUT_DIM + dd], accS);
                    if (dd == 0) atomicAdd(&g_cnt[cur], accG);
                    accS = 0.0f; accG = 0.0f; cur = b;
                }
                float hv = __ldg(hcol + (size_t)n * NODE_DIM);
                float g  = sh_gate[n];
                accS = fmaf(g, hv, accS);
                if (dd == 0) accG += g;
            }
            atomicAdd(&g_S[(size_t)cur * OUT_DIM + dd], accS);
            if (dd == 0) atomicAdd(&g_cnt[cur], accG);
        }
    }
}

// ---------------------------------------------------------------------------
// Final: out[g] = S[g] @ W_p + cnt[g] * b_p for 32 graphs per block,
// 4 independent accumulators per thread; then re-zero this block's slice.
// ---------------------------------------------------------------------------
#define FIN_GRAPHS 32
#define WPT_STRIDE 132   // padded float stride: conflict-free LDS.128

__global__ __launch_bounds__(THREADS, 1)
void final_kernel(const float* __restrict__ Wp,
                  const float* __restrict__ bp,
                  float* __restrict__ out)
{
    extern __shared__ float smf[];
    float* sWpT = smf;                       // 128*132 = 16896 floats (67584B)
    float* sS   = smf + NODE_DIM * WPT_STRIDE;  // 8*132 floats (4224B)
    float* scnt = sS + 8 * WPT_STRIDE;          // 8 floats

    const int tid  = threadIdx.x;
    const int o    = tid & 127;
    const int slot = tid >> 7;    // 0 or 1

    // stage Wp transposed: sWpT[o*132+d] = Wp[d*128+o]
    #pragma unroll 8
    for (int i = tid; i < NODE_DIM * OUT_DIM; i += THREADS) {
        int dd = i >> 7, oo = i & 127;
        sWpT[oo * WPT_STRIDE + dd] = Wp[i];
    }

    const float bpo = bp[o];
    const int gblk = blockIdx.x * FIN_GRAPHS;

    #pragma unroll
    for (int c = 0; c < 4; ++c) {
        // stage 8 S rows (2 slots x 4 graphs) + counts
        __syncthreads();
        {
            int r = tid >> 5, q = tid & 31;          // r 0..7, q 0..31
            int g = gblk + (r >> 2) * 16 + c * 4 + (r & 3);
            ((float4*)(sS + r * WPT_STRIDE))[q] =
                ((const float4*)(g_S + (size_t)g * NODE_DIM))[q];
            if (tid < 8) {
                int gg = gblk + (tid >> 2) * 16 + c * 4 + (tid & 3);
                scnt[tid] = g_cnt[gg];
            }
        }
        __syncthreads();

        float acc0 = scnt[slot * 4 + 0] * bpo;
        float acc1 = scnt[slot * 4 + 1] * bpo;
        float acc2 = scnt[slot * 4 + 2] * bpo;
        float acc3 = scnt[slot * 4 + 3] * bpo;

        const float* wrow = sWpT + o * WPT_STRIDE;
        const float* s0 = sS + (slot * 4 + 0) * WPT_STRIDE;
        const float* s1 = sS + (slot * 4 + 1) * WPT_STRIDE;
        const float* s2 = sS + (slot * 4 + 2) * WPT_STRIDE;
        const float* s3 = sS + (slot * 4 + 3) * WPT_STRIDE;

        #pragma unroll
        for (int dd = 0; dd < NODE_DIM; dd += 4) {
            float4 w  = *(const float4*)(wrow + dd);
            float4 v0 = *(const float4*)(s0 + dd);
            float4 v1 = *(const float4*)(s1 + dd);
            float4 v2 = *(const float4*)(s2 + dd);
            float4 v3 = *(const float4*)(s3 + dd);
            acc0 = fmaf(v0.x, w.x, acc0); acc0 = fmaf(v0.y, w.y, acc0);
            acc0 = fmaf(v0.z, w.z, acc0); acc0 = fmaf(v0.w, w.w, acc0);
            acc1 = fmaf(v1.x, w.x, acc1); acc1 = fmaf(v1.y, w.y, acc1);
            acc1 = fmaf(v1.z, w.z, acc1); acc1 = fmaf(v1.w, w.w, acc1);
            acc2 = fmaf(v2.x, w.x, acc2); acc2 = fmaf(v2.y, w.y, acc2);
            acc2 = fmaf(v2.z, w.z, acc2); acc2 = fmaf(v2.w, w.w, acc2);
            acc3 = fmaf(v3.x, w.x, acc3); acc3 = fmaf(v3.y, w.y, acc3);
            acc3 = fmaf(v3.z, w.z, acc3); acc3 = fmaf(v3.w, w.w, acc3);
        }

        int gb = gblk + slot * 16 + c * 4;
        out[(size_t)(gb + 0) * OUT_DIM + o] = acc0;
        out[(size_t)(gb + 1) * OUT_DIM + o] = acc1;
        out[(size_t)(gb + 2) * OUT_DIM + o] = acc2;
        out[(size_t)(gb + 3) * OUT_DIM + o] = acc3;
    }

    // re-zero this block's exclusive slice (all stages are behind the last
    // barrier; compute reads only smem)
    float4 z = make_float4(0.f, 0.f, 0.f, 0.f);
    float4* srow4 = (float4*)(g_S + (size_t)gblk * NODE_DIM);
    #pragma unroll 4
    for (int i = tid; i < FIN_GRAPHS * NODE_DIM / 4; i += THREADS) srow4[i] = z;
    if (tid < FIN_GRAPHS) g_cnt[gblk + tid] = 0.0f;
}

// ---------------------------------------------------------------------------
extern "C" void kernel_launch(void* const* d_in, const int* in_sizes, int n_in,
                              void* d_out, int out_size)
{
    const float* h_nodes = (const float*)d_in[0];
    const void*  batch   = d_in[1];
    const float* Wg1     = (const float*)d_in[2];
    const float* bg1     = (const float*)d_in[3];
    const float* Wg2     = (const float*)d_in[4];
    const float* bg2     = (const float*)d_in[5];
    const float* Wp      = (const float*)d_in[6];
    const float* bp      = (const float*)d_in[7];
    float* out = (float*)d_out;

    const int N = in_sizes[0] / NODE_DIM;

    const int fused_smem = 53760;
    const int final_smem = (NODE_DIM * WPT_STRIDE + 8 * WPT_STRIDE + 8) * 4;

    cudaFuncSetAttribute(fused_kernel, cudaFuncAttributeMaxDynamicSharedMemorySize, fused_smem);
    cudaFuncSetAttribute(final_kernel, cudaFuncAttributeMaxDynamicSharedMemorySize, final_smem);

    prep_kernel<<<1, THREADS>>>(Wg1);
    {
        int blocks = (N + CHUNK - 1) / CHUNK;
        fused_kernel<<<blocks, THREADS, fused_smem>>>(h_nodes, batch, bg1, Wg2, bg2, N);
    }
    {
        final_kernel<<<NUM_GRAPHS / FIN_GRAPHS, THREADS, final_smem>>>(Wp, bp, out);
    }
}

// round 9
// speedup vs baseline: 4.7601x; 1.2408x over previous
#include <cuda_runtime.h>
#include <cuda_fp16.h>
#include <stdint.h>

#define NODE_DIM   128
#define GATE_HID   64
#define OUT_DIM    128
#define NUM_GRAPHS 16384
#define CHUNK      128
#define THREADS    256

#define B_STRIDE_H 136   // halves; 272B row stride, conflict-free fragment LDS

// Scratch: per-graph sum of g*h [B,128] and per-graph sum of g [B].
// Invariant: zero at kernel_launch entry. Loader zero-init covers call #1;
// final_kernel re-zeros its exclusive slice after consuming it.
__device__ float g_S[NUM_GRAPHS * OUT_DIM];
__device__ float g_cnt[NUM_GRAPHS];
// Pre-converted fp16 Wg1^T in the exact MMA smem layout (64 rows x 136 stride)
__device__ __half g_B16[GATE_HID * B_STRIDE_H];

static __device__ __forceinline__ uint32_t u32_of(__half2 h) {
    union { __half2 h; uint32_t u; } c; c.h = h; return c.u;
}
static __device__ __forceinline__ uint32_t cvt2(float2 v) {
    return u32_of(__floats2half2_rn(v.x, v.y));
}

// ---------------------------------------------------------------------------
// Warp-level fp16 MMA: D[16,8] += A[16,16] * B[16,8], fp32 accumulate
// ---------------------------------------------------------------------------
static __device__ __forceinline__ void mma16816(
    float* d, uint32_t a0, uint32_t a1, uint32_t a2, uint32_t a3,
    uint32_t b0, uint32_t b1)
{
    asm volatile(
        "mma.sync.aligned.m16n8k16.row.col.f32.f16.f16.f32 "
        "{%0,%1,%2,%3}, {%4,%5,%6,%7}, {%8,%9}, {%0,%1,%2,%3};"
        : "+f"(d[0]), "+f"(d[1]), "+f"(d[2]), "+f"(d[3])
        : "r"(a0), "r"(a1), "r"(a2), "r"(a3), "r"(b0), "r"(b1));
}

// batch may be int32 or int64: int32 view of index N-1 (odd) is the zero high
// word under int64 layout, the last (~16383) sorted id under int32 layout.
static __device__ __forceinline__ int batch_at(const void* p, int i, bool is64) {
    if (is64) return (int)(((const long long*)p)[i]);
    return ((const int*)p)[i];
}

// ---------------------------------------------------------------------------
// prep: Wg1 [128,64] -> fp16 B tile [n][k] in padded layout (zeros in pad)
// ---------------------------------------------------------------------------
__global__ void prep_kernel(const float* __restrict__ Wg1) {
    int idx = blockIdx.x * blockDim.x + threadIdx.x;
    if (idx < GATE_HID * B_STRIDE_H) {
        int n = idx / B_STRIDE_H, k = idx % B_STRIDE_H;
        __half v = __float2half_rn(0.0f);
        if (k < NODE_DIM) v = __float2half_rn(Wg1[k * GATE_HID + n]);
        g_B16[idx] = v;
    }
}

// ---------------------------------------------------------------------------
// Fused pass per 128-node chunk. No A staging: fragments loaded straight from
// global with inline cvt; per-warp scatter with shfl-broadcast gates.
// ---------------------------------------------------------------------------
__global__ __launch_bounds__(THREADS, 4)
void fused_kernel(const float* __restrict__ h_nodes,
                  const void*  __restrict__ batch,
                  const float* __restrict__ bg1,
                  const float* __restrict__ Wg2,
                  const float* __restrict__ bg2,
                  int N)
{
    __shared__ __half smB[GATE_HID * B_STRIDE_H];   // 17408 B
    __shared__ int    sh_b[CHUNK];
    __shared__ float  sh_w2[GATE_HID];
    __shared__ float  sh_b1[GATE_HID];

    const int tid  = threadIdx.x;
    const int wid  = tid >> 5;
    const int lane = tid & 31;
    const int gq   = lane >> 2;   // fragment row group 0..7
    const int tq   = lane & 3;    // fragment quad 0..3
    const int base = blockIdx.x * CHUNK;
    const int nn   = min(CHUNK, N - base);

    const bool is64 = (((const int*)batch)[N - 1] == 0);

    // stage B tile (1088 uint4), ids, small vectors
    #pragma unroll 5
    for (int i = tid; i < GATE_HID * B_STRIDE_H / 8; i += THREADS)
        ((uint4*)smB)[i] = ((const uint4*)g_B16)[i];
    if (tid < GATE_HID) { sh_w2[tid] = Wg2[tid]; sh_b1[tid] = bg1[tid]; }
    if (tid < CHUNK) sh_b[tid] = (tid < nn) ? batch_at(batch, base + tid, is64) : 0;
    __syncthreads();

    // --- MMA: warp computes rows [wid*16, wid*16+16) x 64 cols, K=128
    // A fragments loaded directly from global (fp32 -> fp16 cvt inline)
    float d[8][4];
    #pragma unroll
    for (int nt = 0; nt < 8; ++nt)
        #pragma unroll
        for (int j = 0; j < 4; ++j) d[nt][j] = 0.0f;

    const int r0 = wid * 16 + gq;
    const float* hr0 = h_nodes + (size_t)(base + r0) * NODE_DIM;
    const float* hr1 = hr0 + 8 * NODE_DIM;
    const bool v0 = (base + r0) < N;
    const bool v1 = (base + r0 + 8) < N;
    const float2 z2 = make_float2(0.f, 0.f);

    #pragma unroll
    for (int ks = 0; ks < 8; ++ks) {
        const int kb = ks * 16 + tq * 2;
        float2 f0 = v0 ? *(const float2*)(hr0 + kb)     : z2;
        float2 f2 = v0 ? *(const float2*)(hr0 + kb + 8) : z2;
        float2 f1 = v1 ? *(const float2*)(hr1 + kb)     : z2;
        float2 f3 = v1 ? *(const float2*)(hr1 + kb + 8) : z2;
        uint32_t a0 = cvt2(f0), a1 = cvt2(f1), a2 = cvt2(f2), a3 = cvt2(f3);
        const __half* Bk = smB + kb;
        #pragma unroll
        for (int nt = 0; nt < 8; ++nt) {
            const __half* Bp = Bk + (nt * 8 + gq) * B_STRIDE_H;
            uint32_t b0 = *(const uint32_t*)Bp;
            uint32_t b1 = *(const uint32_t*)(Bp + 8);
            mma16816(d[nt], a0, a1, a2, a3, b0, b1);
        }
    }

    // --- gate epilogue: relu(+b1) . w2, quad butterfly -> s0,s1 on ALL lanes
    float s0 = 0.0f, s1 = 0.0f;
    #pragma unroll
    for (int nt = 0; nt < 8; ++nt) {
        int c0 = nt * 8 + tq * 2;
        float b1a = sh_b1[c0], b1b = sh_b1[c0 + 1];
        float w2a = sh_w2[c0], w2b = sh_w2[c0 + 1];
        s0 = fmaf(fmaxf(d[nt][0] + b1a, 0.0f), w2a, s0);
        s0 = fmaf(fmaxf(d[nt][1] + b1b, 0.0f), w2b, s0);
        s1 = fmaf(fmaxf(d[nt][2] + b1a, 0.0f), w2a, s1);
        s1 = fmaf(fmaxf(d[nt][3] + b1b, 0.0f), w2b, s1);
    }
    s0 += __shfl_xor_sync(0xffffffffu, s0, 1);
    s0 += __shfl_xor_sync(0xffffffffu, s0, 2);
    s1 += __shfl_xor_sync(0xffffffffu, s1, 1);
    s1 += __shfl_xor_sync(0xffffffffu, s1, 2);
    {
        float b2 = bg2[0];
        s0 = 1.0f / (1.0f + __expf(-(s0 + b2)));   // gate row gq
        s1 = 1.0f / (1.0f + __expf(-(s1 + b2)));   // gate row gq+8
    }

    // --- per-warp scatter: this warp's 16 nodes x 128 dims (lane = 4 dims).
    // Gates broadcast via shfl; h re-read from global (L1/L2-hot), exact fp32.
    {
        const int nbeg = wid * 16;
        const int nend = min(nbeg + 16, nn);
        if (nbeg < nend) {
            float a0 = 0.f, a1 = 0.f, a2 = 0.f, a3 = 0.f, accG = 0.f;
            int cur = sh_b[nbeg];
            #pragma unroll
            for (int lr = 0; lr < 16; ++lr) {
                int n = nbeg + lr;
                if (n >= nend) break;
                int b = sh_b[n];
                if (b != cur) {
                    float* dst = g_S + (size_t)cur * OUT_DIM + lane * 4;
                    atomicAdd(dst + 0, a0); atomicAdd(dst + 1, a1);
                    atomicAdd(dst + 2, a2); atomicAdd(dst + 3, a3);
                    if (lane == 0) atomicAdd(&g_cnt[cur], accG);
                    a0 = a1 = a2 = a3 = 0.f; accG = 0.f; cur = b;
                }
                float g = __shfl_sync(0xffffffffu, (lr < 8) ? s0 : s1, (lr & 7) * 4);
                float4 hv = *(const float4*)(h_nodes
                              + (size_t)(base + n) * NODE_DIM + lane * 4);
                a0 = fmaf(g, hv.x, a0); a1 = fmaf(g, hv.y, a1);
                a2 = fmaf(g, hv.z, a2); a3 = fmaf(g, hv.w, a3);
                accG += g;
            }
            float* dst = g_S + (size_t)cur * OUT_DIM + lane * 4;
            atomicAdd(dst + 0, a0); atomicAdd(dst + 1, a1);
            atomicAdd(dst + 2, a2); atomicAdd(dst + 3, a3);
            if (lane == 0) atomicAdd(&g_cnt[cur], accG);
        }
    }
}

// ---------------------------------------------------------------------------
// Final: out[g] = S[g] @ W_p + cnt[g] * b_p, 32 graphs/block, 4 acc/thread;
// then re-zero this block's exclusive slice of the scratch.
// ---------------------------------------------------------------------------
#define FIN_GRAPHS 32
#define WPT_STRIDE 132   // padded float stride: conflict-free LDS.128

__global__ __launch_bounds__(THREADS, 1)
void final_kernel(const float* __restrict__ Wp,
                  const float* __restrict__ bp,
                  float* __restrict__ out)
{
    extern __shared__ float smf[];
    float* sWpT = smf;                          // 128*132 floats
    float* sS   = smf + NODE_DIM * WPT_STRIDE;  // 8*132 floats
    float* scnt = sS + 8 * WPT_STRIDE;          // 8 floats

    const int tid  = threadIdx.x;
    const int o    = tid & 127;
    const int slot = tid >> 7;    // 0 or 1

    #pragma unroll 8
    for (int i = tid; i < NODE_DIM * OUT_DIM; i += THREADS) {
        int dd = i >> 7, oo = i & 127;
        sWpT[oo * WPT_STRIDE + dd] = Wp[i];
    }

    const float bpo = bp[o];
    const int gblk = blockIdx.x * FIN_GRAPHS;

    #pragma unroll
    for (int c = 0; c < 4; ++c) {
        __syncthreads();
        {
            int r = tid >> 5, q = tid & 31;
            int g = gblk + (r >> 2) * 16 + c * 4 + (r & 3);
            ((float4*)(sS + r * WPT_STRIDE))[q] =
                ((const float4*)(g_S + (size_t)g * NODE_DIM))[q];
            if (tid < 8) {
                int gg = gblk + (tid >> 2) * 16 + c * 4 + (tid & 3);
                scnt[tid] = g_cnt[gg];
            }
        }
        __syncthreads();

        float acc0 = scnt[slot * 4 + 0] * bpo;
        float acc1 = scnt[slot * 4 + 1] * bpo;
        float acc2 = scnt[slot * 4 + 2] * bpo;
        float acc3 = scnt[slot * 4 + 3] * bpo;

        const float* wrow = sWpT + o * WPT_STRIDE;
        const float* s0 = sS + (slot * 4 + 0) * WPT_STRIDE;
        const float* s1 = sS + (slot * 4 + 1) * WPT_STRIDE;
        const float* s2 = sS + (slot * 4 + 2) * WPT_STRIDE;
        const float* s3 = sS + (slot * 4 + 3) * WPT_STRIDE;

        #pragma unroll
        for (int dd = 0; dd < NODE_DIM; dd += 4) {
            float4 w  = *(const float4*)(wrow + dd);
            float4 v0 = *(const float4*)(s0 + dd);
            float4 v1 = *(const float4*)(s1 + dd);
            float4 v2 = *(const float4*)(s2 + dd);
            float4 v3 = *(const float4*)(s3 + dd);
            acc0 = fmaf(v0.x, w.x, acc0); acc0 = fmaf(v0.y, w.y, acc0);
            acc0 = fmaf(v0.z, w.z, acc0); acc0 = fmaf(v0.w, w.w, acc0);
            acc1 = fmaf(v1.x, w.x, acc1); acc1 = fmaf(v1.y, w.y, acc1);
            acc1 = fmaf(v1.z, w.z, acc1); acc1 = fmaf(v1.w, w.w, acc1);
            acc2 = fmaf(v2.x, w.x, acc2); acc2 = fmaf(v2.y, w.y, acc2);
            acc2 = fmaf(v2.z, w.z, acc2); acc2 = fmaf(v2.w, w.w, acc2);
            acc3 = fmaf(v3.x, w.x, acc3); acc3 = fmaf(v3.y, w.y, acc3);
            acc3 = fmaf(v3.z, w.z, acc3); acc3 = fmaf(v3.w, w.w, acc3);
        }

        int gb = gblk + slot * 16 + c * 4;
        out[(size_t)(gb + 0) * OUT_DIM + o] = acc0;
        out[(size_t)(gb + 1) * OUT_DIM + o] = acc1;
        out[(size_t)(gb + 2) * OUT_DIM + o] = acc2;
        out[(size_t)(gb + 3) * OUT_DIM + o] = acc3;
    }

    __syncthreads();
    float4 z = make_float4(0.f, 0.f, 0.f, 0.f);
    float4* srow4 = (float4*)(g_S + (size_t)gblk * NODE_DIM);
    #pragma unroll 4
    for (int i = tid; i < FIN_GRAPHS * NODE_DIM / 4; i += THREADS) srow4[i] = z;
    if (tid < FIN_GRAPHS) g_cnt[gblk + tid] = 0.0f;
}

// ---------------------------------------------------------------------------
extern "C" void kernel_launch(void* const* d_in, const int* in_sizes, int n_in,
                              void* d_out, int out_size)
{
    const float* h_nodes = (const float*)d_in[0];
    const void*  batch   = d_in[1];
    const float* Wg1     = (const float*)d_in[2];
    const float* bg1     = (const float*)d_in[3];
    const float* Wg2     = (const float*)d_in[4];
    const float* bg2     = (const float*)d_in[5];
    const float* Wp      = (const float*)d_in[6];
    const float* bp      = (const float*)d_in[7];
    float* out = (float*)d_out;

    const int N = in_sizes[0] / NODE_DIM;

    const int final_smem = (NODE_DIM * WPT_STRIDE + 8 * WPT_STRIDE + 8) * 4;
    cudaFuncSetAttribute(final_kernel, cudaFuncAttributeMaxDynamicSharedMemorySize, final_smem);

    {
        int total = GATE_HID * B_STRIDE_H;
        prep_kernel<<<(total + THREADS - 1) / THREADS, THREADS>>>(Wg1);
    }
    {
        int blocks = (N + CHUNK - 1) / CHUNK;
        fused_kernel<<<blocks, THREADS>>>(h_nodes, batch, bg1, Wg2, bg2, N);
    }
    {
        final_kernel<<<NUM_GRAPHS / FIN_GRAPHS, THREADS, final_smem>>>(Wp, bp, out);
    }
}

// round 10
// speedup vs baseline: 4.8091x; 1.0103x over previous
#include <cuda_runtime.h>
#include <cuda_fp16.h>
#include <stdint.h>

#define NODE_DIM   128
#define GATE_HID   64
#define OUT_DIM    128
#define NUM_GRAPHS 16384
#define CHUNK      256
#define THREADS    256

#define B_STRIDE_H 136   // halves; 272B row stride
#define A_SLICE_H  (16 * B_STRIDE_H)   // warp-private fp16 h slice (16 rows)

// Scratch: per-graph sum of g*h [B,128] and per-graph sum of g [B].
// Invariant: zero at kernel_launch entry. Loader zero-init covers call #1;
// final_kernel re-zeros its exclusive slice after consuming it.
__device__ float g_S[NUM_GRAPHS * OUT_DIM];
__device__ float g_cnt[NUM_GRAPHS];
// Pre-converted fp16 Wg1^T (64 rows x 136 stride)
__device__ __half g_B16[GATE_HID * B_STRIDE_H];

static __device__ __forceinline__ uint32_t u32_of(__half2 h) {
    union { __half2 h; uint32_t u; } c; c.h = h; return c.u;
}
static __device__ __forceinline__ uint32_t cvt2(float2 v) {
    return u32_of(__floats2half2_rn(v.x, v.y));
}

// ---------------------------------------------------------------------------
// Warp-level fp16 MMA: D[16,8] += A[16,16] * B[16,8], fp32 accumulate
// ---------------------------------------------------------------------------
static __device__ __forceinline__ void mma16816(
    float* d, uint32_t a0, uint32_t a1, uint32_t a2, uint32_t a3,
    uint32_t b0, uint32_t b1)
{
    asm volatile(
        "mma.sync.aligned.m16n8k16.row.col.f32.f16.f16.f32 "
        "{%0,%1,%2,%3}, {%4,%5,%6,%7}, {%8,%9}, {%0,%1,%2,%3};"
        : "+f"(d[0]), "+f"(d[1]), "+f"(d[2]), "+f"(d[3])
        : "r"(a0), "r"(a1), "r"(a2), "r"(a3), "r"(b0), "r"(b1));
}

// batch may be int32 or int64: int32 view of index N-1 (odd) is the zero high
// word under int64 layout, the last (~16383) sorted id under int32 layout.
static __device__ __forceinline__ int batch_at(const void* p, int i, bool is64) {
    if (is64) return (int)(((const long long*)p)[i]);
    return ((const int*)p)[i];
}

// ---------------------------------------------------------------------------
// prep: Wg1 [128,64] -> fp16 B tile [n][k] in padded layout (zeros in pad)
// ---------------------------------------------------------------------------
__global__ void prep_kernel(const float* __restrict__ Wg1) {
    int idx = blockIdx.x * blockDim.x + threadIdx.x;
    if (idx < GATE_HID * B_STRIDE_H) {
        int n = idx / B_STRIDE_H, k = idx % B_STRIDE_H;
        __half v = __float2half_rn(0.0f);
        if (k < NODE_DIM) v = __float2half_rn(Wg1[k * GATE_HID + n]);
        g_B16[idx] = v;
    }
}

// ---------------------------------------------------------------------------
// Fused pass per 256-node chunk; each warp owns 32 rows as 2 sub-tiles of 16.
// Per sub-tile: load h from global ONCE (fp32->fp16 cvt inline), store fp16 to
// a warp-private smem slice, run MMAs, epilogue, scatter from the smem slice.
// No cross-warp sync after the initial B staging.
// ---------------------------------------------------------------------------
__global__ __launch_bounds__(THREADS, 4)
void fused_kernel(const float* __restrict__ h_nodes,
                  const void*  __restrict__ batch,
                  const float* __restrict__ bg1,
                  const float* __restrict__ Wg2,
                  const float* __restrict__ bg2,
                  int N)
{
    extern __shared__ char sm[];
    __half* smB  = (__half*)sm;                            // 17408 B
    __half* smHA = (__half*)(sm + 17408);                  // 8*4352 = 34816 B
    int*    sh_b = (int*)(sm + 52224);                     // 1024 B
    float*  sh_w2 = (float*)(sm + 53248);                  // 256 B
    float*  sh_b1 = (float*)(sm + 53504);                  // 256 B
                                                           // total 53760

    const int tid  = threadIdx.x;
    const int wid  = tid >> 5;
    const int lane = tid & 31;
    const int gq   = lane >> 2;   // fragment row group 0..7
    const int tq   = lane & 3;    // fragment quad 0..3
    const int base = blockIdx.x * CHUNK;
    const int nn   = min(CHUNK, N - base);

    const bool is64 = (((const int*)batch)[N - 1] == 0);

    // stage B tile (1088 uint4), ids, small vectors
    #pragma unroll 5
    for (int i = tid; i < GATE_HID * B_STRIDE_H / 8; i += THREADS)
        ((uint4*)smB)[i] = ((const uint4*)g_B16)[i];
    if (tid < GATE_HID) { sh_w2[tid] = Wg2[tid]; sh_b1[tid] = bg1[tid]; }
    if (tid < CHUNK) sh_b[tid] = (tid < nn) ? batch_at(batch, base + tid, is64) : 0;
    __syncthreads();

    __half* ws = smHA + wid * A_SLICE_H;   // this warp's 16-row fp16 slice
    const float b2 = bg2[0];

    for (int sub = 0; sub < 2; ++sub) {
        const int rbeg = wid * 32 + sub * 16;          // block-local first row
        // --- MMA with inline global->fp16 conversion + smem store
        float d[8][4];
        #pragma unroll
        for (int nt = 0; nt < 8; ++nt)
            #pragma unroll
            for (int j = 0; j < 4; ++j) d[nt][j] = 0.0f;

        const int r0 = rbeg + gq;
        const float* hr0 = h_nodes + (size_t)(base + r0) * NODE_DIM;
        const float* hr1 = hr0 + 8 * NODE_DIM;
        const bool v0 = (base + r0) < N;
        const bool v1 = (base + r0 + 8) < N;
        const float2 z2 = make_float2(0.f, 0.f);

        #pragma unroll
        for (int ks = 0; ks < 8; ++ks) {
            const int kb = ks * 16 + tq * 2;
            float2 f0 = v0 ? *(const float2*)(hr0 + kb)     : z2;
            float2 f2 = v0 ? *(const float2*)(hr0 + kb + 8) : z2;
            float2 f1 = v1 ? *(const float2*)(hr1 + kb)     : z2;
            float2 f3 = v1 ? *(const float2*)(hr1 + kb + 8) : z2;
            uint32_t a0 = cvt2(f0), a1 = cvt2(f1), a2 = cvt2(f2), a3 = cvt2(f3);
            // stash fp16 h for the scatter (warp-private slice rows 0..15)
            *(uint32_t*)(ws + gq * B_STRIDE_H + kb)           = a0;
            *(uint32_t*)(ws + gq * B_STRIDE_H + kb + 8)       = a2;
            *(uint32_t*)(ws + (gq + 8) * B_STRIDE_H + kb)     = a1;
            *(uint32_t*)(ws + (gq + 8) * B_STRIDE_H + kb + 8) = a3;
            const __half* Bk = smB + kb;
            #pragma unroll
            for (int nt = 0; nt < 8; ++nt) {
                const __half* Bp = Bk + (nt * 8 + gq) * B_STRIDE_H;
                uint32_t b0 = *(const uint32_t*)Bp;
                uint32_t b1 = *(const uint32_t*)(Bp + 8);
                mma16816(d[nt], a0, a1, a2, a3, b0, b1);
            }
        }

        // --- gate epilogue: relu(+b1) . w2, quad butterfly -> s0,s1 all lanes
        float s0 = 0.0f, s1 = 0.0f;
        #pragma unroll
        for (int nt = 0; nt < 8; ++nt) {
            int c0 = nt * 8 + tq * 2;
            float b1a = sh_b1[c0], b1b = sh_b1[c0 + 1];
            float w2a = sh_w2[c0], w2b = sh_w2[c0 + 1];
            s0 = fmaf(fmaxf(d[nt][0] + b1a, 0.0f), w2a, s0);
            s0 = fmaf(fmaxf(d[nt][1] + b1b, 0.0f), w2b, s0);
            s1 = fmaf(fmaxf(d[nt][2] + b1a, 0.0f), w2a, s1);
            s1 = fmaf(fmaxf(d[nt][3] + b1b, 0.0f), w2b, s1);
        }
        s0 += __shfl_xor_sync(0xffffffffu, s0, 1);
        s0 += __shfl_xor_sync(0xffffffffu, s0, 2);
        s1 += __shfl_xor_sync(0xffffffffu, s1, 1);
        s1 += __shfl_xor_sync(0xffffffffu, s1, 2);
        s0 = 1.0f / (1.0f + __expf(-(s0 + b2)));   // gate rows rbeg+gq
        s1 = 1.0f / (1.0f + __expf(-(s1 + b2)));   // gate rows rbeg+gq+8

        // --- per-warp scatter of these 16 nodes (lane = 4 dims); h from the
        // warp-private fp16 slice (conflict-free 256B row reads).
        const int nend = min(rbeg + 16, nn);
        if (rbeg < nend) {
            float a0 = 0.f, a1 = 0.f, a2 = 0.f, a3 = 0.f, accG = 0.f;
            int cur = sh_b[rbeg];
            #pragma unroll
            for (int lr = 0; lr < 16; ++lr) {
                int n = rbeg + lr;
                if (n >= nend) break;
                int b = sh_b[n];
                if (b != cur) {
                    float* dst = g_S + (size_t)cur * OUT_DIM + lane * 4;
                    atomicAdd(dst + 0, a0); atomicAdd(dst + 1, a1);
                    atomicAdd(dst + 2, a2); atomicAdd(dst + 3, a3);
                    if (lane == 0) atomicAdd(&g_cnt[cur], accG);
                    a0 = a1 = a2 = a3 = 0.f; accG = 0.f; cur = b;
                }
                float g = __shfl_sync(0xffffffffu, (lr < 8) ? s0 : s1, (lr & 7) * 4);
                const __half2* hp = (const __half2*)(ws + lr * B_STRIDE_H + lane * 4);
                float2 h01 = __half22float2(hp[0]);
                float2 h23 = __half22float2(hp[1]);
                a0 = fmaf(g, h01.x, a0); a1 = fmaf(g, h01.y, a1);
                a2 = fmaf(g, h23.x, a2); a3 = fmaf(g, h23.y, a3);
                accG += g;
            }
            float* dst = g_S + (size_t)cur * OUT_DIM + lane * 4;
            atomicAdd(dst + 0, a0); atomicAdd(dst + 1, a1);
            atomicAdd(dst + 2, a2); atomicAdd(dst + 3, a3);
            if (lane == 0) atomicAdd(&g_cnt[cur], accG);
        }
    }
}

// ---------------------------------------------------------------------------
// Final: out[g] = S[g] @ W_p + cnt[g] * b_p, 32 graphs/block, 4 acc/thread;
// then re-zero this block's exclusive slice of the scratch.
// ---------------------------------------------------------------------------
#define FIN_GRAPHS 32
#define WPT_STRIDE 132   // padded float stride: conflict-free LDS.128

__global__ __launch_bounds__(THREADS, 1)
void final_kernel(const float* __restrict__ Wp,
                  const float* __restrict__ bp,
                  float* __restrict__ out)
{
    extern __shared__ float smf[];
    float* sWpT = smf;                          // 128*132 floats
    float* sS   = smf + NODE_DIM * WPT_STRIDE;  // 8*132 floats
    float* scnt = sS + 8 * WPT_STRIDE;          // 8 floats

    const int tid  = threadIdx.x;
    const int o    = tid & 127;
    const int slot = tid >> 7;    // 0 or 1

    #pragma unroll 8
    for (int i = tid; i < NODE_DIM * OUT_DIM; i += THREADS) {
        int dd = i >> 7, oo = i & 127;
        sWpT[oo * WPT_STRIDE + dd] = Wp[i];
    }

    const float bpo = bp[o];
    const int gblk = blockIdx.x * FIN_GRAPHS;

    #pragma unroll
    for (int c = 0; c < 4; ++c) {
        __syncthreads();
        {
            int r = tid >> 5, q = tid & 31;
            int g = gblk + (r >> 2) * 16 + c * 4 + (r & 3);
            ((float4*)(sS + r * WPT_STRIDE))[q] =
                ((const float4*)(g_S + (size_t)g * NODE_DIM))[q];
            if (tid < 8) {
                int gg = gblk + (tid >> 2) * 16 + c * 4 + (tid & 3);
                scnt[tid] = g_cnt[gg];
            }
        }
        __syncthreads();

        float acc0 = scnt[slot * 4 + 0] * bpo;
        float acc1 = scnt[slot * 4 + 1] * bpo;
        float acc2 = scnt[slot * 4 + 2] * bpo;
        float acc3 = scnt[slot * 4 + 3] * bpo;

        const float* wrow = sWpT + o * WPT_STRIDE;
        const float* s0 = sS + (slot * 4 + 0) * WPT_STRIDE;
        const float* s1 = sS + (slot * 4 + 1) * WPT_STRIDE;
        const float* s2 = sS + (slot * 4 + 2) * WPT_STRIDE;
        const float* s3 = sS + (slot * 4 + 3) * WPT_STRIDE;

        #pragma unroll
        for (int dd = 0; dd < NODE_DIM; dd += 4) {
            float4 w  = *(const float4*)(wrow + dd);
            float4 v0 = *(const float4*)(s0 + dd);
            float4 v1 = *(const float4*)(s1 + dd);
            float4 v2 = *(const float4*)(s2 + dd);
            float4 v3 = *(const float4*)(s3 + dd);
            acc0 = fmaf(v0.x, w.x, acc0); acc0 = fmaf(v0.y, w.y, acc0);
            acc0 = fmaf(v0.z, w.z, acc0); acc0 = fmaf(v0.w, w.w, acc0);
            acc1 = fmaf(v1.x, w.x, acc1); acc1 = fmaf(v1.y, w.y, acc1);
            acc1 = fmaf(v1.z, w.z, acc1); acc1 = fmaf(v1.w, w.w, acc1);
            acc2 = fmaf(v2.x, w.x, acc2); acc2 = fmaf(v2.y, w.y, acc2);
            acc2 = fmaf(v2.z, w.z, acc2); acc2 = fmaf(v2.w, w.w, acc2);
            acc3 = fmaf(v3.x, w.x, acc3); acc3 = fmaf(v3.y, w.y, acc3);
            acc3 = fmaf(v3.z, w.z, acc3); acc3 = fmaf(v3.w, w.w, acc3);
        }

        int gb = gblk + slot * 16 + c * 4;
        out[(size_t)(gb + 0) * OUT_DIM + o] = acc0;
        out[(size_t)(gb + 1) * OUT_DIM + o] = acc1;
        out[(size_t)(gb + 2) * OUT_DIM + o] = acc2;
        out[(size_t)(gb + 3) * OUT_DIM + o] = acc3;
    }

    __syncthreads();
    float4 z = make_float4(0.f, 0.f, 0.f, 0.f);
    float4* srow4 = (float4*)(g_S + (size_t)gblk * NODE_DIM);
    #pragma unroll 4
    for (int i = tid; i < FIN_GRAPHS * NODE_DIM / 4; i += THREADS) srow4[i] = z;
    if (tid < FIN_GRAPHS) g_cnt[gblk + tid] = 0.0f;
}

// ---------------------------------------------------------------------------
extern "C" void kernel_launch(void* const* d_in, const int* in_sizes, int n_in,
                              void* d_out, int out_size)
{
    const float* h_nodes = (const float*)d_in[0];
    const void*  batch   = d_in[1];
    const float* Wg1     = (const float*)d_in[2];
    const float* bg1     = (const float*)d_in[3];
    const float* Wg2     = (const float*)d_in[4];
    const float* bg2     = (const float*)d_in[5];
    const float* Wp      = (const float*)d_in[6];
    const float* bp      = (const float*)d_in[7];
    float* out = (float*)d_out;

    const int N = in_sizes[0] / NODE_DIM;

    const int fused_smem = 53760;
    const int final_smem = (NODE_DIM * WPT_STRIDE + 8 * WPT_STRIDE + 8) * 4;
    cudaFuncSetAttribute(fused_kernel, cudaFuncAttributeMaxDynamicSharedMemorySize, fused_smem);
    cudaFuncSetAttribute(final_kernel, cudaFuncAttributeMaxDynamicSharedMemorySize, final_smem);

    {
        int total = GATE_HID * B_STRIDE_H;
        prep_kernel<<<(total + THREADS - 1) / THREADS, THREADS>>>(Wg1);
    }
    {
        int blocks = (N + CHUNK - 1) / CHUNK;
        fused_kernel<<<blocks, THREADS, fused_smem>>>(h_nodes, batch, bg1, Wg2, bg2, N);
    }
    {
        final_kernel<<<NUM_GRAPHS / FIN_GRAPHS, THREADS, final_smem>>>(Wp, bp, out);
    }
}

// round 11
// speedup vs baseline: 4.9614x; 1.0317x over previous
#include <cuda_runtime.h>
#include <cuda_fp16.h>
#include <stdint.h>

#define NODE_DIM   128
#define GATE_HID   64
#define OUT_DIM    128
#define NUM_GRAPHS 16384
#define CHUNK      256
#define THREADS    256

#define B_STRIDE_H 136   // halves; 272B row stride
#define A_SLICE_H  (16 * B_STRIDE_H)   // warp-private fp16 h slice (16 rows)

// Scratch: per-graph sum of g*h [B,128] and per-graph sum of g [B].
// Invariant: zero at kernel_launch entry. Loader zero-init covers call #1;
// final_kernel re-zeros its exclusive slice after consuming it.
__device__ float g_S[NUM_GRAPHS * OUT_DIM];
__device__ float g_cnt[NUM_GRAPHS];
// Pre-converted fp16 Wg1^T (64 rows x 136 stride)
__device__ __half g_B16[GATE_HID * B_STRIDE_H];

static __device__ __forceinline__ uint32_t u32_of(__half2 h) {
    union { __half2 h; uint32_t u; } c; c.h = h; return c.u;
}
static __device__ __forceinline__ uint32_t cvt2(float2 v) {
    return u32_of(__floats2half2_rn(v.x, v.y));
}

// ---------------------------------------------------------------------------
// Warp-level fp16 MMA: D[16,8] += A[16,16] * B[16,8], fp32 accumulate
// ---------------------------------------------------------------------------
static __device__ __forceinline__ void mma16816(
    float* d, uint32_t a0, uint32_t a1, uint32_t a2, uint32_t a3,
    uint32_t b0, uint32_t b1)
{
    asm volatile(
        "mma.sync.aligned.m16n8k16.row.col.f32.f16.f16.f32 "
        "{%0,%1,%2,%3}, {%4,%5,%6,%7}, {%8,%9}, {%0,%1,%2,%3};"
        : "+f"(d[0]), "+f"(d[1]), "+f"(d[2]), "+f"(d[3])
        : "r"(a0), "r"(a1), "r"(a2), "r"(a3), "r"(b0), "r"(b1));
}

// batch may be int32 or int64: int32 view of index N-1 (odd) is the zero high
// word under int64 layout, the last (~16383) sorted id under int32 layout.
static __device__ __forceinline__ int batch_at(const void* p, int i, bool is64) {
    if (is64) return (int)(((const long long*)p)[i]);
    return ((const int*)p)[i];
}

// ---------------------------------------------------------------------------
// prep: Wg1 [128,64] -> fp16 B tile [n][k] in padded layout (zeros in pad)
// ---------------------------------------------------------------------------
__global__ void prep_kernel(const float* __restrict__ Wg1) {
    int idx = blockIdx.x * blockDim.x + threadIdx.x;
    if (idx < GATE_HID * B_STRIDE_H) {
        int n = idx / B_STRIDE_H, k = idx % B_STRIDE_H;
        __half v = __float2half_rn(0.0f);
        if (k < NODE_DIM) v = __float2half_rn(Wg1[k * GATE_HID + n]);
        g_B16[idx] = v;
    }
}

// ---------------------------------------------------------------------------
// Fused pass per 256-node chunk; each warp owns 32 rows as 2 sub-tiles of 16.
// Per sub-tile the K loop runs as 2 groups of 4 ks-steps with phase-separated
// load(16x LDG.64, MLP=16) -> cvt+STS -> MMA so DRAM latency is pipelined.
// Scatter reads h as fp16 from the warp-private smem slice (single HBM read).
// ---------------------------------------------------------------------------
__global__ __launch_bounds__(THREADS, 3)
void fused_kernel(const float* __restrict__ h_nodes,
                  const void*  __restrict__ batch,
                  const float* __restrict__ bg1,
                  const float* __restrict__ Wg2,
                  const float* __restrict__ bg2,
                  int N)
{
    extern __shared__ char sm[];
    __half* smB  = (__half*)sm;                            // 17408 B
    __half* smHA = (__half*)(sm + 17408);                  // 8*4352 = 34816 B
    int*    sh_b = (int*)(sm + 52224);                     // 1024 B
    float*  sh_w2 = (float*)(sm + 53248);                  // 256 B
    float*  sh_b1 = (float*)(sm + 53504);                  // 256 B
                                                           // total 53760

    const int tid  = threadIdx.x;
    const int wid  = tid >> 5;
    const int lane = tid & 31;
    const int gq   = lane >> 2;   // fragment row group 0..7
    const int tq   = lane & 3;    // fragment quad 0..3
    const int base = blockIdx.x * CHUNK;
    const int nn   = min(CHUNK, N - base);

    const bool is64 = (((const int*)batch)[N - 1] == 0);

    // stage B tile (1088 uint4), ids, small vectors
    #pragma unroll 5
    for (int i = tid; i < GATE_HID * B_STRIDE_H / 8; i += THREADS)
        ((uint4*)smB)[i] = ((const uint4*)g_B16)[i];
    if (tid < GATE_HID) { sh_w2[tid] = Wg2[tid]; sh_b1[tid] = bg1[tid]; }
    if (tid < CHUNK) sh_b[tid] = (tid < nn) ? batch_at(batch, base + tid, is64) : 0;
    __syncthreads();

    __half* ws = smHA + wid * A_SLICE_H;   // this warp's 16-row fp16 slice
    const float b2 = bg2[0];

    for (int sub = 0; sub < 2; ++sub) {
        const int rbeg = wid * 32 + sub * 16;          // block-local first row
        float d[8][4];
        #pragma unroll
        for (int nt = 0; nt < 8; ++nt)
            #pragma unroll
            for (int j = 0; j < 4; ++j) d[nt][j] = 0.0f;

        const int r0 = rbeg + gq;
        const float* hr0 = h_nodes + (size_t)(base + r0) * NODE_DIM;
        const float* hr1 = hr0 + 8 * NODE_DIM;
        const bool v0 = (base + r0) < N;
        const bool v1 = (base + r0 + 8) < N;
        const float2 z2 = make_float2(0.f, 0.f);

        #pragma unroll
        for (int grp = 0; grp < 2; ++grp) {
            // ---- phase 1: batch all 16 loads of this group (MLP = 16)
            float2 f0[4], f1[4], f2[4], f3[4];
            #pragma unroll
            for (int kk = 0; kk < 4; ++kk) {
                const int kb = (grp * 4 + kk) * 16 + tq * 2;
                f0[kk] = v0 ? *(const float2*)(hr0 + kb)     : z2;
                f2[kk] = v0 ? *(const float2*)(hr0 + kb + 8) : z2;
                f1[kk] = v1 ? *(const float2*)(hr1 + kb)     : z2;
                f3[kk] = v1 ? *(const float2*)(hr1 + kb + 8) : z2;
            }
            // ---- phase 2: convert + stash fp16 to warp slice
            uint32_t A0[4], A1[4], A2[4], A3[4];
            #pragma unroll
            for (int kk = 0; kk < 4; ++kk) {
                A0[kk] = cvt2(f0[kk]); A1[kk] = cvt2(f1[kk]);
                A2[kk] = cvt2(f2[kk]); A3[kk] = cvt2(f3[kk]);
                const int kb = (grp * 4 + kk) * 16 + tq * 2;
                *(uint32_t*)(ws + gq * B_STRIDE_H + kb)           = A0[kk];
                *(uint32_t*)(ws + gq * B_STRIDE_H + kb + 8)       = A2[kk];
                *(uint32_t*)(ws + (gq + 8) * B_STRIDE_H + kb)     = A1[kk];
                *(uint32_t*)(ws + (gq + 8) * B_STRIDE_H + kb + 8) = A3[kk];
            }
            // ---- phase 3: MMAs
            #pragma unroll
            for (int kk = 0; kk < 4; ++kk) {
                const int kb = (grp * 4 + kk) * 16 + tq * 2;
                const __half* Bk = smB + kb;
                #pragma unroll
                for (int nt = 0; nt < 8; ++nt) {
                    const __half* Bp = Bk + (nt * 8 + gq) * B_STRIDE_H;
                    uint32_t b0 = *(const uint32_t*)Bp;
                    uint32_t b1 = *(const uint32_t*)(Bp + 8);
                    mma16816(d[nt], A0[kk], A1[kk], A2[kk], A3[kk], b0, b1);
                }
            }
        }

        // --- gate epilogue: relu(+b1) . w2, quad butterfly -> s0,s1 all lanes
        float s0 = 0.0f, s1 = 0.0f;
        #pragma unroll
        for (int nt = 0; nt < 8; ++nt) {
            int c0 = nt * 8 + tq * 2;
            float b1a = sh_b1[c0], b1b = sh_b1[c0 + 1];
            float w2a = sh_w2[c0], w2b = sh_w2[c0 + 1];
            s0 = fmaf(fmaxf(d[nt][0] + b1a, 0.0f), w2a, s0);
            s0 = fmaf(fmaxf(d[nt][1] + b1b, 0.0f), w2b, s0);
            s1 = fmaf(fmaxf(d[nt][2] + b1a, 0.0f), w2a, s1);
            s1 = fmaf(fmaxf(d[nt][3] + b1b, 0.0f), w2b, s1);
        }
        s0 += __shfl_xor_sync(0xffffffffu, s0, 1);
        s0 += __shfl_xor_sync(0xffffffffu, s0, 2);
        s1 += __shfl_xor_sync(0xffffffffu, s1, 1);
        s1 += __shfl_xor_sync(0xffffffffu, s1, 2);
        s0 = 1.0f / (1.0f + __expf(-(s0 + b2)));   // gate rows rbeg+gq
        s1 = 1.0f / (1.0f + __expf(-(s1 + b2)));   // gate rows rbeg+gq+8

        // --- per-warp scatter of these 16 nodes (lane = 4 dims); h from the
        // warp-private fp16 slice (conflict-free 256B row reads).
        const int nend = min(rbeg + 16, nn);
        if (rbeg < nend) {
            float a0 = 0.f, a1 = 0.f, a2 = 0.f, a3 = 0.f, accG = 0.f;
            int cur = sh_b[rbeg];
            #pragma unroll
            for (int lr = 0; lr < 16; ++lr) {
                int n = rbeg + lr;
                if (n >= nend) break;
                int b = sh_b[n];
                if (b != cur) {
                    float* dst = g_S + (size_t)cur * OUT_DIM + lane * 4;
                    atomicAdd(dst + 0, a0); atomicAdd(dst + 1, a1);
                    atomicAdd(dst + 2, a2); atomicAdd(dst + 3, a3);
                    if (lane == 0) atomicAdd(&g_cnt[cur], accG);
                    a0 = a1 = a2 = a3 = 0.f; accG = 0.f; cur = b;
                }
                float g = __shfl_sync(0xffffffffu, (lr < 8) ? s0 : s1, (lr & 7) * 4);
                const __half2* hp = (const __half2*)(ws + lr * B_STRIDE_H + lane * 4);
                float2 h01 = __half22float2(hp[0]);
                float2 h23 = __half22float2(hp[1]);
                a0 = fmaf(g, h01.x, a0); a1 = fmaf(g, h01.y, a1);
                a2 = fmaf(g, h23.x, a2); a3 = fmaf(g, h23.y, a3);
                accG += g;
            }
            float* dst = g_S + (size_t)cur * OUT_DIM + lane * 4;
            atomicAdd(dst + 0, a0); atomicAdd(dst + 1, a1);
            atomicAdd(dst + 2, a2); atomicAdd(dst + 3, a3);
            if (lane == 0) atomicAdd(&g_cnt[cur], accG);
        }
    }
}

// ---------------------------------------------------------------------------
// Final: out[g] = S[g] @ W_p + cnt[g] * b_p, 32 graphs/block, 4 acc/thread;
// then re-zero this block's exclusive slice of the scratch.
// ---------------------------------------------------------------------------
#define FIN_GRAPHS 32
#define WPT_STRIDE 132   // padded float stride: conflict-free LDS.128

__global__ __launch_bounds__(THREADS, 1)
void final_kernel(const float* __restrict__ Wp,
                  const float* __restrict__ bp,
                  float* __restrict__ out)
{
    extern __shared__ float smf[];
    float* sWpT = smf;                          // 128*132 floats
    float* sS   = smf + NODE_DIM * WPT_STRIDE;  // 8*132 floats
    float* scnt = sS + 8 * WPT_STRIDE;          // 8 floats

    const int tid  = threadIdx.x;
    const int o    = tid & 127;
    const int slot = tid >> 7;    // 0 or 1

    #pragma unroll 8
    for (int i = tid; i < NODE_DIM * OUT_DIM; i += THREADS) {
        int dd = i >> 7, oo = i & 127;
        sWpT[oo * WPT_STRIDE + dd] = Wp[i];
    }

    const float bpo = bp[o];
    const int gblk = blockIdx.x * FIN_GRAPHS;

    #pragma unroll
    for (int c = 0; c < 4; ++c) {
        __syncthreads();
        {
            int r = tid >> 5, q = tid & 31;
            int g = gblk + (r >> 2) * 16 + c * 4 + (r & 3);
            ((float4*)(sS + r * WPT_STRIDE))[q] =
                ((const float4*)(g_S + (size_t)g * NODE_DIM))[q];
            if (tid < 8) {
                int gg = gblk + (tid >> 2) * 16 + c * 4 + (tid & 3);
                scnt[tid] = g_cnt[gg];
            }
        }
        __syncthreads();

        float acc0 = scnt[slot * 4 + 0] * bpo;
        float acc1 = scnt[slot * 4 + 1] * bpo;
        float acc2 = scnt[slot * 4 + 2] * bpo;
        float acc3 = scnt[slot * 4 + 3] * bpo;

        const float* wrow = sWpT + o * WPT_STRIDE;
        const float* s0 = sS + (slot * 4 + 0) * WPT_STRIDE;
        const float* s1 = sS + (slot * 4 + 1) * WPT_STRIDE;
        const float* s2 = sS + (slot * 4 + 2) * WPT_STRIDE;
        const float* s3 = sS + (slot * 4 + 3) * WPT_STRIDE;

        #pragma unroll
        for (int dd = 0; dd < NODE_DIM; dd += 4) {
            float4 w  = *(const float4*)(wrow + dd);
            float4 v0 = *(const float4*)(s0 + dd);
            float4 v1 = *(const float4*)(s1 + dd);
            float4 v2 = *(const float4*)(s2 + dd);
            float4 v3 = *(const float4*)(s3 + dd);
            acc0 = fmaf(v0.x, w.x, acc0); acc0 = fmaf(v0.y, w.y, acc0);
            acc0 = fmaf(v0.z, w.z, acc0); acc0 = fmaf(v0.w, w.w, acc0);
            acc1 = fmaf(v1.x, w.x, acc1); acc1 = fmaf(v1.y, w.y, acc1);
            acc1 = fmaf(v1.z, w.z, acc1); acc1 = fmaf(v1.w, w.w, acc1);
            acc2 = fmaf(v2.x, w.x, acc2); acc2 = fmaf(v2.y, w.y, acc2);
            acc2 = fmaf(v2.z, w.z, acc2); acc2 = fmaf(v2.w, w.w, acc2);
            acc3 = fmaf(v3.x, w.x, acc3); acc3 = fmaf(v3.y, w.y, acc3);
            acc3 = fmaf(v3.z, w.z, acc3); acc3 = fmaf(v3.w, w.w, acc3);
        }

        int gb = gblk + slot * 16 + c * 4;
        out[(size_t)(gb + 0) * OUT_DIM + o] = acc0;
        out[(size_t)(gb + 1) * OUT_DIM + o] = acc1;
        out[(size_t)(gb + 2) * OUT_DIM + o] = acc2;
        out[(size_t)(gb + 3) * OUT_DIM + o] = acc3;
    }

    __syncthreads();
    float4 z = make_float4(0.f, 0.f, 0.f, 0.f);
    float4* srow4 = (float4*)(g_S + (size_t)gblk * NODE_DIM);
    #pragma unroll 4
    for (int i = tid; i < FIN_GRAPHS * NODE_DIM / 4; i += THREADS) srow4[i] = z;
    if (tid < FIN_GRAPHS) g_cnt[gblk + tid] = 0.0f;
}

// ---------------------------------------------------------------------------
extern "C" void kernel_launch(void* const* d_in, const int* in_sizes, int n_in,
                              void* d_out, int out_size)
{
    const float* h_nodes = (const float*)d_in[0];
    const void*  batch   = d_in[1];
    const float* Wg1     = (const float*)d_in[2];
    const float* bg1     = (const float*)d_in[3];
    const float* Wg2     = (const float*)d_in[4];
    const float* bg2     = (const float*)d_in[5];
    const float* Wp      = (const float*)d_in[6];
    const float* bp      = (const float*)d_in[7];
    float* out = (float*)d_out;

    const int N = in_sizes[0] / NODE_DIM;

    const int fused_smem = 53760;
    const int final_smem = (NODE_DIM * WPT_STRIDE + 8 * WPT_STRIDE + 8) * 4;
    cudaFuncSetAttribute(fused_kernel, cudaFuncAttributeMaxDynamicSharedMemorySize, fused_smem);
    cudaFuncSetAttribute(final_kernel, cudaFuncAttributeMaxDynamicSharedMemorySize, final_smem);

    {
        int total = GATE_HID * B_STRIDE_H;
        prep_kernel<<<(total + THREADS - 1) / THREADS, THREADS>>>(Wg1);
    }
    {
        int blocks = (N + CHUNK - 1) / CHUNK;
        fused_kernel<<<blocks, THREADS, fused_smem>>>(h_nodes, batch, bg1, Wg2, bg2, N);
    }
    {
        final_kernel<<<NUM_GRAPHS / FIN_GRAPHS, THREADS, final_smem>>>(Wp, bp, out);
    }
}